// round 1
// baseline (speedup 1.0000x reference)
#include <cuda_runtime.h>

// ---------------- problem-size bounds (fixed by the dataset) ----------------
#define NMAX 20000
#define EMAX 320000
#define DH   128     // node embedding dim
#define HEADS 4
#define HD   512     // HEADS * DH

// ---------------- device scratch (no allocations allowed) -------------------
__device__ float g_hidden[NMAX * 256];   // encoder hidden
__device__ float g_h0[NMAX * DH];        // encoder out
__device__ float g_h1[NMAX * DH];        // layer1 out
__device__ float g_hlin[NMAX * HD];      // h @ lin  (per layer, reused)
__device__ float g_as[NMAX * HEADS];
__device__ float g_ad[NMAX * HEADS];
__device__ int   g_cnt[NMAX];
__device__ int   g_ctr[NMAX];
__device__ int   g_rowptr[NMAX + 1];
__device__ int   g_csrc[EMAX];
__device__ int   g_ctype[EMAX];
__device__ float g_relproj[2 * 26 * HEADS];   // [layer][26][4]

// ---------------- small utility kernels -------------------------------------
__global__ void zero2_kernel(int* a, int* b, int n) {
    int i = blockIdx.x * blockDim.x + threadIdx.x;
    if (i < n) { a[i] = 0; b[i] = 0; }
}

__global__ void hist_kernel(const int* __restrict__ dst, int E, int* __restrict__ cnt) {
    int i = blockIdx.x * blockDim.x + threadIdx.x;
    if (i < E) atomicAdd(&cnt[dst[i]], 1);
}

// single-block exclusive scan of cnt[0..n) -> rowptr[0..n]
__global__ void scan_kernel(const int* __restrict__ cnt, int* __restrict__ rowptr, int n) {
    __shared__ int part[1024];
    int tid = threadIdx.x;
    int chunk = (n + 1023) / 1024;
    int b = tid * chunk;
    int e = min(b + chunk, n);
    int s = 0;
    for (int i = b; i < e; i++) s += cnt[i];
    part[tid] = s;
    __syncthreads();
    // Hillis-Steele inclusive scan
    for (int off = 1; off < 1024; off <<= 1) {
        int v = (tid >= off) ? part[tid - off] : 0;
        __syncthreads();
        part[tid] += v;
        __syncthreads();
    }
    int run = (tid == 0) ? 0 : part[tid - 1];
    for (int i = b; i < e; i++) { rowptr[i] = run; run += cnt[i]; }
    if (tid == 0) rowptr[n] = part[1023];
}

__global__ void scatter_kernel(const int* __restrict__ src, const int* __restrict__ dst,
                               const int* __restrict__ type, int E,
                               const int* __restrict__ rowptr, int* __restrict__ ctr,
                               int* __restrict__ csrc, int* __restrict__ ctype) {
    int i = blockIdx.x * blockDim.x + threadIdx.x;
    if (i < E) {
        int d = dst[i];
        int p = rowptr[d] + atomicAdd(&ctr[d], 1);
        csrc[p]  = src[i];
        ctype[p] = type[i];
    }
}

// relproj[r][h] = sum_k rel_emb[r,k] * (sum_d line[k, h*128+d] * atte[h,d])
__global__ void relproj_kernel(const float* __restrict__ rel_emb,
                               const float* __restrict__ line,
                               const float* __restrict__ atte,
                               float* __restrict__ relproj) {
    __shared__ float we[32 * HEADS];
    int tid = threadIdx.x;   // 128 threads
    {
        int k = tid >> 2, h = tid & 3;
        float s = 0.f;
        const float* lp = line + k * HD + h * DH;
        const float* ap = atte + h * DH;
        for (int d = 0; d < DH; d++) s += lp[d] * ap[d];
        we[k * HEADS + h] = s;
    }
    __syncthreads();
    if (tid < 26 * HEADS) {
        int r = tid >> 2, h = tid & 3;
        float s = 0.f;
        for (int k = 0; k < 32; k++) s += rel_emb[r * 32 + k] * we[k * HEADS + h];
        relproj[tid] = s;
    }
}

// ---------------- tiled fp32 GEMM: C = act(A[M,K] @ B[K,N] + bias) ----------
template <bool RELU, bool HAS_BIAS>
__global__ void sgemm128(int M, int N, int K,
                         const float* __restrict__ A, const float* __restrict__ B,
                         const float* __restrict__ bias, float* __restrict__ C) {
    constexpr int BM = 128, BN = 128, BK = 16, TM = 8, TN = 8;
    __shared__ float As[BK][BM + 4];
    __shared__ float Bs[BK][BN];
    const int tid = threadIdx.x;           // 256 threads
    const int bm = blockIdx.y * BM, bn = blockIdx.x * BN;
    const int trow = (tid / 16) * TM;
    const int tcol = (tid % 16) * TN;
    float acc[TM][TN] = {};
    float ra[TM], rb[TN];

    for (int kt = 0; kt < K; kt += BK) {
#pragma unroll
        for (int i = 0; i < 8; i++) {      // BM*BK = 2048 / 256 = 8 per thread
            int idx = tid + i * 256;
            int r = idx / BK, c = idx % BK;
            int gr = bm + r, gc = kt + c;
            As[c][r] = (gr < M && gc < K) ? A[(long)gr * K + gc] : 0.f;
        }
#pragma unroll
        for (int i = 0; i < 8; i++) {      // BK*BN = 2048 / 256 = 8 per thread
            int idx = tid + i * 256;
            int r = idx / BN, c = idx % BN;
            int gr = kt + r, gc = bn + c;
            Bs[r][c] = (gr < K && gc < N) ? B[(long)gr * N + gc] : 0.f;
        }
        __syncthreads();
#pragma unroll
        for (int k = 0; k < BK; k++) {
#pragma unroll
            for (int i = 0; i < TM; i++) ra[i] = As[k][trow + i];
#pragma unroll
            for (int j = 0; j < TN; j++) rb[j] = Bs[k][tcol + j];
#pragma unroll
            for (int i = 0; i < TM; i++)
#pragma unroll
                for (int j = 0; j < TN; j++) acc[i][j] += ra[i] * rb[j];
        }
        __syncthreads();
    }
#pragma unroll
    for (int i = 0; i < TM; i++) {
        int gr = bm + trow + i;
        if (gr >= M) continue;
#pragma unroll
        for (int j = 0; j < TN; j++) {
            int gc = bn + tcol + j;
            float v = acc[i][j];
            if (HAS_BIAS) v += bias[gc];
            if (RELU) v = fmaxf(v, 0.f);
            C[(long)gr * N + gc] = v;
        }
    }
}

// ---------------- per-node attention score precompute ------------------------
// a_s[n,h] = dot(hlin[n, h*128: ], atts[h,:]); same for a_d.
__global__ void attdot_kernel(const float* __restrict__ hlin,
                              const float* __restrict__ atts,
                              const float* __restrict__ attd,
                              float* __restrict__ as_, float* __restrict__ ad_) {
    int n = blockIdx.x;
    int w = threadIdx.x >> 5, lane = threadIdx.x & 31;
    const float* h = hlin + (long)n * HD + w * DH;
    const float* sp = atts + w * DH;
    const float* dp = attd + w * DH;
    float vs = 0.f, vd = 0.f;
#pragma unroll
    for (int i = lane; i < DH; i += 32) {
        float hv = h[i];
        vs += hv * sp[i];
        vd += hv * dp[i];
    }
#pragma unroll
    for (int off = 16; off > 0; off >>= 1) {
        vs += __shfl_down_sync(0xffffffffu, vs, off);
        vd += __shfl_down_sync(0xffffffffu, vd, off);
    }
    if (lane == 0) {
        as_[n * HEADS + w] = vs;
        ad_[n * HEADS + w] = vd;
    }
}

// ---------------- GAT aggregation: softmax over incoming edges + self loop ---
// One block (128 threads) per destination node. thread = output dim d.
__global__ void gat_agg_kernel(const float* __restrict__ hlin,
                               const float* __restrict__ a_s,
                               const float* __restrict__ a_d,
                               const int* __restrict__ rowptr,
                               const int* __restrict__ csrc,
                               const int* __restrict__ ctype,
                               const float* __restrict__ relproj,
                               const float* __restrict__ bias,
                               float* __restrict__ out) {
    const int n = blockIdx.x;
    const int tid = threadIdx.x;   // 128

    __shared__ float s_rp[26 * HEADS];
    __shared__ float red_m[128 * HEADS];
    __shared__ float red_s[128 * HEADS];
    __shared__ float red_r[128 * HEADS];
    __shared__ float s_alpha[128 * HEADS];
    __shared__ int   s_src[128];
    __shared__ float s_m[HEADS], s_inv[HEADS], s_la[HEADS];

    if (tid < 26 * HEADS) s_rp[tid] = relproj[tid];
    const int beg = rowptr[n], end = rowptr[n + 1];
    const int deg = end - beg;
    float ad[HEADS];
#pragma unroll
    for (int h = 0; h < HEADS; h++) ad[h] = a_d[n * HEADS + h];
    __syncthreads();

    // ---- phase A: online softmax stats over real edges ----
    float m[HEADS], ssum[HEADS], srl[HEADS];
#pragma unroll
    for (int h = 0; h < HEADS; h++) { m[h] = -1e30f; ssum[h] = 0.f; srl[h] = 0.f; }
    for (int e = beg + tid; e < end; e += 128) {
        int sp = csrc[e] * HEADS;
        int tp = ctype[e] * HEADS;
#pragma unroll
        for (int h = 0; h < HEADS; h++) {
            float rp = s_rp[tp + h];
            float l = a_s[sp + h] + ad[h] + rp;
            l = (l > 0.f) ? l : 0.2f * l;
            srl[h] += rp;
            if (l > m[h]) { ssum[h] = ssum[h] * __expf(m[h] - l) + 1.f; m[h] = l; }
            else          { ssum[h] += __expf(l - m[h]); }
        }
    }
#pragma unroll
    for (int h = 0; h < HEADS; h++) {
        red_m[tid * HEADS + h] = m[h];
        red_s[tid * HEADS + h] = ssum[h];
        red_r[tid * HEADS + h] = srl[h];
    }
    __syncthreads();

    if (tid < HEADS) {
        int h = tid;
        float M = -1e30f, S = 0.f, R = 0.f;
        for (int i = 0; i < 128; i++) {
            float mi = red_m[i * HEADS + h], si = red_s[i * HEADS + h];
            R += red_r[i * HEADS + h];
            if (mi > M) { S = S * __expf(M - mi) + si; M = mi; }
            else        { S += si * __expf(mi - M); }
        }
        // self loop: a_e = mean of rel_proj over incoming edges
        float lae = R / (float)max(deg, 1);
        float l = a_s[n * HEADS + h] + ad[h] + lae;
        l = (l > 0.f) ? l : 0.2f * l;
        if (l > M) { S = S * __expf(M - l) + 1.f; M = l; }
        else       { S += __expf(l - M); }
        float inv = 1.f / (S + 1e-16f);
        s_m[h] = M;
        s_inv[h] = inv;
        s_la[h] = __expf(l - M) * inv;
    }
    __syncthreads();

    float mh[HEADS], inv[HEADS];
#pragma unroll
    for (int h = 0; h < HEADS; h++) { mh[h] = s_m[h]; inv[h] = s_inv[h]; }

    // ---- phase B: weighted accumulation. thread tid owns output dim d=tid.
    float acc[HEADS];
    {
        const float* hn = hlin + (long)n * HD + tid;
#pragma unroll
        for (int h = 0; h < HEADS; h++) acc[h] = s_la[h] * hn[h * DH];
    }
    for (int base = beg; base < end; base += 128) {
        int e = base + tid;
        if (e < end) {
            int sp = csrc[e];
            int tp = ctype[e] * HEADS;
            s_src[tid] = sp;
#pragma unroll
            for (int h = 0; h < HEADS; h++) {
                float l = a_s[sp * HEADS + h] + ad[h] + s_rp[tp + h];
                l = (l > 0.f) ? l : 0.2f * l;
                s_alpha[tid * HEADS + h] = __expf(l - mh[h]) * inv[h];
            }
        }
        __syncthreads();
        int cn = min(128, end - base);
        for (int j = 0; j < cn; j++) {
            const float* hs = hlin + (long)s_src[j] * HD + tid;
            float a0 = s_alpha[j * HEADS + 0];
            float a1 = s_alpha[j * HEADS + 1];
            float a2 = s_alpha[j * HEADS + 2];
            float a3 = s_alpha[j * HEADS + 3];
            acc[0] += a0 * hs[0 * DH];
            acc[1] += a1 * hs[1 * DH];
            acc[2] += a2 * hs[2 * DH];
            acc[3] += a3 * hs[3 * DH];
        }
        __syncthreads();
    }
    float o = 0.25f * (acc[0] + acc[1] + acc[2] + acc[3]) + bias[tid];
    o = fmaxf(o, 0.f);   // both GAT layers are followed by relu
    out[(long)n * DH + tid] = o;
}

// ---------------- launch ------------------------------------------------------
extern "C" void kernel_launch(void* const* d_in, const int* in_sizes, int n_in,
                              void* d_out, int out_size) {
    const float* x     = (const float*)d_in[0];
    const int*   eidx  = (const int*)d_in[1];
    const int*   etype = (const int*)d_in[2];
    const float* w1    = (const float*)d_in[3];
    const float* b1    = (const float*)d_in[4];
    const float* w2    = (const float*)d_in[5];
    const float* b2    = (const float*)d_in[6];
    const float* rel   = (const float*)d_in[7];
    const float* lin1  = (const float*)d_in[8];
    const float* line1 = (const float*)d_in[9];
    const float* atts1 = (const float*)d_in[10];
    const float* attd1 = (const float*)d_in[11];
    const float* atte1 = (const float*)d_in[12];
    const float* bias1 = (const float*)d_in[13];
    const float* lin2  = (const float*)d_in[14];
    const float* line2 = (const float*)d_in[15];
    const float* atts2 = (const float*)d_in[16];
    const float* attd2 = (const float*)d_in[17];
    const float* atte2 = (const float*)d_in[18];
    const float* bias2 = (const float*)d_in[19];

    const int N = out_size / DH;          // 20000
    const int E = in_sizes[1] / 2;        // 320000
    const int F = in_sizes[3] / 256;      // 518
    const int* src = eidx;
    const int* dst = eidx + E;

    float *hidden, *h0, *h1, *hlin, *as_, *ad_, *relproj;
    int *cnt, *ctr, *rowptr, *csrc, *ctype;
    cudaGetSymbolAddress((void**)&hidden, g_hidden);
    cudaGetSymbolAddress((void**)&h0, g_h0);
    cudaGetSymbolAddress((void**)&h1, g_h1);
    cudaGetSymbolAddress((void**)&hlin, g_hlin);
    cudaGetSymbolAddress((void**)&as_, g_as);
    cudaGetSymbolAddress((void**)&ad_, g_ad);
    cudaGetSymbolAddress((void**)&cnt, g_cnt);
    cudaGetSymbolAddress((void**)&ctr, g_ctr);
    cudaGetSymbolAddress((void**)&rowptr, g_rowptr);
    cudaGetSymbolAddress((void**)&csrc, g_csrc);
    cudaGetSymbolAddress((void**)&ctype, g_ctype);
    cudaGetSymbolAddress((void**)&relproj, g_relproj);

    // CSR build (same for both layers)
    zero2_kernel<<<(N + 255) / 256, 256>>>(cnt, ctr, N);
    hist_kernel<<<(E + 255) / 256, 256>>>(dst, E, cnt);
    scan_kernel<<<1, 1024>>>(cnt, rowptr, N);
    scatter_kernel<<<(E + 255) / 256, 256>>>(src, dst, etype, E, rowptr, ctr, csrc, ctype);

    // collapsed edge-attention tables
    relproj_kernel<<<1, 128>>>(rel, line1, atte1, relproj);
    relproj_kernel<<<1, 128>>>(rel, line2, atte2, relproj + 26 * HEADS);

    // node encoder
    {
        dim3 g(256 / 128, (N + 127) / 128);
        sgemm128<true, true><<<g, 256>>>(N, 256, F, x, w1, b1, hidden);
    }
    {
        dim3 g(1, (N + 127) / 128);
        sgemm128<false, true><<<g, 256>>>(N, DH, 256, hidden, w2, b2, h0);
    }

    // GAT layer 1
    {
        dim3 g(HD / 128, (N + 127) / 128);
        sgemm128<false, false><<<g, 256>>>(N, HD, DH, h0, lin1, nullptr, hlin);
    }
    attdot_kernel<<<N, 128>>>(hlin, atts1, attd1, as_, ad_);
    gat_agg_kernel<<<N, 128>>>(hlin, as_, ad_, rowptr, csrc, ctype,
                               relproj, bias1, h1);

    // GAT layer 2
    {
        dim3 g(HD / 128, (N + 127) / 128);
        sgemm128<false, false><<<g, 256>>>(N, HD, DH, h1, lin2, nullptr, hlin);
    }
    attdot_kernel<<<N, 128>>>(hlin, atts2, attd2, as_, ad_);
    gat_agg_kernel<<<N, 128>>>(hlin, as_, ad_, rowptr, csrc, ctype,
                               relproj + 26 * HEADS, bias2, (float*)d_out);
}

// round 2
// speedup vs baseline: 1.5874x; 1.5874x over previous
#include <cuda_runtime.h>
#include <cstdint>

// ---------------- problem-size bounds (fixed by the dataset) ----------------
#define NMAX 20000
#define EMAX 320000
#define DH   128     // node embedding dim
#define HEADS 4
#define HD   512     // HEADS * DH

// ---------------- device scratch (no allocations allowed) -------------------
__device__ float g_hidden[NMAX * 256];   // encoder hidden
__device__ float g_h0[NMAX * DH];        // encoder out
__device__ float g_h1[NMAX * DH];        // layer1 out
__device__ float g_hlin[NMAX * HD];      // h @ lin  (per layer, reused)
__device__ float g_as[NMAX * HEADS];
__device__ float g_ad[NMAX * HEADS];
__device__ int   g_cnt[NMAX];
__device__ int   g_ctr[NMAX];
__device__ int   g_rowptr[NMAX + 1];
__device__ int   g_csrc[EMAX];
__device__ int   g_ctype[EMAX];
__device__ float g_relproj[2 * 26 * HEADS];   // [layer][26][4]

// ---------------- small utility kernels -------------------------------------
__global__ void zero2_kernel(int* a, int* b, int n) {
    int i = blockIdx.x * blockDim.x + threadIdx.x;
    if (i < n) { a[i] = 0; b[i] = 0; }
}

__global__ void hist_kernel(const int* __restrict__ dst, int E, int* __restrict__ cnt) {
    int i = blockIdx.x * blockDim.x + threadIdx.x;
    if (i < E) atomicAdd(&cnt[dst[i]], 1);
}

// single-block exclusive scan of cnt[0..n) -> rowptr[0..n]
__global__ void scan_kernel(const int* __restrict__ cnt, int* __restrict__ rowptr, int n) {
    __shared__ int part[1024];
    int tid = threadIdx.x;
    int chunk = (n + 1023) / 1024;
    int b = tid * chunk;
    int e = min(b + chunk, n);
    int s = 0;
    for (int i = b; i < e; i++) s += cnt[i];
    part[tid] = s;
    __syncthreads();
    for (int off = 1; off < 1024; off <<= 1) {
        int v = (tid >= off) ? part[tid - off] : 0;
        __syncthreads();
        part[tid] += v;
        __syncthreads();
    }
    int run = (tid == 0) ? 0 : part[tid - 1];
    for (int i = b; i < e; i++) { rowptr[i] = run; run += cnt[i]; }
    if (tid == 0) rowptr[n] = part[1023];
}

__global__ void scatter_kernel(const int* __restrict__ src, const int* __restrict__ dst,
                               const int* __restrict__ type, int E,
                               const int* __restrict__ rowptr, int* __restrict__ ctr,
                               int* __restrict__ csrc, int* __restrict__ ctype) {
    int i = blockIdx.x * blockDim.x + threadIdx.x;
    if (i < E) {
        int d = dst[i];
        int p = rowptr[d] + atomicAdd(&ctr[d], 1);
        csrc[p]  = src[i];
        ctype[p] = type[i];
    }
}

// relproj[r][h] = sum_k rel_emb[r,k] * (sum_d line[k, h*128+d] * atte[h,d])
__global__ void relproj_kernel(const float* __restrict__ rel_emb,
                               const float* __restrict__ line,
                               const float* __restrict__ atte,
                               float* __restrict__ relproj) {
    __shared__ float we[32 * HEADS];
    int tid = threadIdx.x;   // 128 threads
    {
        int k = tid >> 2, h = tid & 3;
        float s = 0.f;
        const float* lp = line + k * HD + h * DH;
        const float* ap = atte + h * DH;
        for (int d = 0; d < DH; d++) s += lp[d] * ap[d];
        we[k * HEADS + h] = s;
    }
    __syncthreads();
    if (tid < 26 * HEADS) {
        int r = tid >> 2, h = tid & 3;
        float s = 0.f;
        for (int k = 0; k < 32; k++) s += rel_emb[r * 32 + k] * we[k * HEADS + h];
        relproj[tid] = s;
    }
}

// ---------------- tf32 tensor-core GEMM -------------------------------------
// C[M,N] = act(A[M,K] @ B[K,N] + bias).  BM=128 BN=128 BK=32, 8 warps.
// Warp grid 2(m) x 4(n): warp tile 64x32 = 4x4 m16n8k8 atoms.
__device__ __forceinline__ uint32_t f2tf32(float f) {
    uint32_t u;
    asm("cvt.rna.tf32.f32 %0, %1;" : "=r"(u) : "f"(f));
    return u;
}

__device__ __forceinline__ void mma_tf32(float c[4], const uint32_t a[4], const uint32_t b[2]) {
    asm volatile(
        "mma.sync.aligned.m16n8k8.row.col.f32.tf32.tf32.f32 "
        "{%0,%1,%2,%3}, {%4,%5,%6,%7}, {%8,%9}, {%0,%1,%2,%3};"
        : "+f"(c[0]), "+f"(c[1]), "+f"(c[2]), "+f"(c[3])
        : "r"(a[0]), "r"(a[1]), "r"(a[2]), "r"(a[3]), "r"(b[0]), "r"(b[1]));
}

template <bool RELU, bool HAS_BIAS>
__global__ __launch_bounds__(256, 2) void mma_gemm(
        int M, int N, int K,
        const float* __restrict__ A, const float* __restrict__ B,
        const float* __restrict__ bias, float* __restrict__ C) {
    constexpr int BM = 128, BN = 128, BK = 32;
    constexpr int AP = 36;    // A smem pitch (floats) -> bank = (4m+k)%32, conflict-free
    constexpr int BP = 136;   // B smem pitch (floats) -> bank = (8k+n)%32, conflict-free
    __shared__ uint32_t As[BM * AP];
    __shared__ uint32_t Bs[BK * BP];

    const int tid  = threadIdx.x;
    const int lane = tid & 31;
    const int warp = tid >> 5;
    const int warpM = warp >> 2;          // 0..1 -> m offset 0/64
    const int warpN = warp & 3;           // 0..3 -> n offset 0/32/64/96
    const int bm = blockIdx.y * BM;
    const int bn = blockIdx.x * BN;
    const int mBase = warpM * 64;
    const int nBase = warpN * 32;
    const int qr = lane >> 2;             // quad row   (0..7)
    const int qc = lane & 3;              // quad col   (0..3)

    float acc[4][4][4] = {};

    for (int kt = 0; kt < K; kt += BK) {
        // load A tile [128 x 32]
#pragma unroll
        for (int i = 0; i < 16; i++) {
            int idx = i * 256 + tid;
            int r = idx >> 5, c = idx & 31;
            int gr = bm + r, gc = kt + c;
            float v = (gr < M && gc < K) ? A[(long)gr * K + gc] : 0.f;
            As[r * AP + c] = f2tf32(v);
        }
        // load B tile [32 x 128]
#pragma unroll
        for (int i = 0; i < 16; i++) {
            int idx = i * 256 + tid;
            int r = idx >> 7, c = idx & 127;
            int gr = kt + r;
            float v = (gr < K) ? B[(long)gr * N + bn + c] : 0.f;
            Bs[r * BP + c] = f2tf32(v);
        }
        __syncthreads();

#pragma unroll
        for (int ks = 0; ks < 4; ks++) {          // 4 x k8 steps
            const int k0 = ks * 8 + qc;
            uint32_t af[4][4], bf[4][2];
#pragma unroll
            for (int am = 0; am < 4; am++) {
                int r0 = mBase + am * 16 + qr;
                af[am][0] = As[r0 * AP + k0];
                af[am][1] = As[(r0 + 8) * AP + k0];
                af[am][2] = As[r0 * AP + k0 + 4];
                af[am][3] = As[(r0 + 8) * AP + k0 + 4];
            }
#pragma unroll
            for (int bnn = 0; bnn < 4; bnn++) {
                int c0 = nBase + bnn * 8 + qr;
                bf[bnn][0] = Bs[k0 * BP + c0];
                bf[bnn][1] = Bs[(k0 + 4) * BP + c0];
            }
#pragma unroll
            for (int am = 0; am < 4; am++)
#pragma unroll
                for (int bnn = 0; bnn < 4; bnn++)
                    mma_tf32(acc[am][bnn], af[am], bf[bnn]);
        }
        __syncthreads();
    }

    // epilogue
#pragma unroll
    for (int am = 0; am < 4; am++) {
        int r0 = bm + mBase + am * 16 + qr;
#pragma unroll
        for (int bnn = 0; bnn < 4; bnn++) {
            int c0 = bn + nBase + bnn * 8 + 2 * qc;
            float b0 = 0.f, b1 = 0.f;
            if (HAS_BIAS) { b0 = bias[c0]; b1 = bias[c0 + 1]; }
#pragma unroll
            for (int half = 0; half < 2; half++) {
                int gr = r0 + half * 8;
                if (gr >= M) continue;
                float v0 = acc[am][bnn][half * 2 + 0] + b0;
                float v1 = acc[am][bnn][half * 2 + 1] + b1;
                if (RELU) { v0 = fmaxf(v0, 0.f); v1 = fmaxf(v1, 0.f); }
                *reinterpret_cast<float2*>(&C[(long)gr * N + c0]) = make_float2(v0, v1);
            }
        }
    }
}

// ---------------- per-node attention score precompute ------------------------
__global__ void attdot_kernel(const float* __restrict__ hlin,
                              const float* __restrict__ atts,
                              const float* __restrict__ attd,
                              float* __restrict__ as_, float* __restrict__ ad_) {
    int n = blockIdx.x;
    int w = threadIdx.x >> 5, lane = threadIdx.x & 31;
    const float* h = hlin + (long)n * HD + w * DH;
    const float* sp = atts + w * DH;
    const float* dp = attd + w * DH;
    float vs = 0.f, vd = 0.f;
#pragma unroll
    for (int i = lane; i < DH; i += 32) {
        float hv = h[i];
        vs += hv * sp[i];
        vd += hv * dp[i];
    }
#pragma unroll
    for (int off = 16; off > 0; off >>= 1) {
        vs += __shfl_down_sync(0xffffffffu, vs, off);
        vd += __shfl_down_sync(0xffffffffu, vd, off);
    }
    if (lane == 0) {
        as_[n * HEADS + w] = vs;
        ad_[n * HEADS + w] = vd;
    }
}

// ---------------- GAT aggregation: softmax over incoming edges + self loop ---
__global__ void gat_agg_kernel(const float* __restrict__ hlin,
                               const float* __restrict__ a_s,
                               const float* __restrict__ a_d,
                               const int* __restrict__ rowptr,
                               const int* __restrict__ csrc,
                               const int* __restrict__ ctype,
                               const float* __restrict__ relproj,
                               const float* __restrict__ bias,
                               float* __restrict__ out) {
    const int n = blockIdx.x;
    const int tid = threadIdx.x;   // 128

    __shared__ float s_rp[26 * HEADS];
    __shared__ float red_m[128 * HEADS];
    __shared__ float red_s[128 * HEADS];
    __shared__ float red_r[128 * HEADS];
    __shared__ float s_alpha[128 * HEADS];
    __shared__ int   s_src[128];
    __shared__ float s_m[HEADS], s_inv[HEADS], s_la[HEADS];

    if (tid < 26 * HEADS) s_rp[tid] = relproj[tid];
    const int beg = rowptr[n], end = rowptr[n + 1];
    const int deg = end - beg;
    float ad[HEADS];
#pragma unroll
    for (int h = 0; h < HEADS; h++) ad[h] = a_d[n * HEADS + h];
    __syncthreads();

    // ---- phase A: online softmax stats over real edges ----
    float m[HEADS], ssum[HEADS], srl[HEADS];
#pragma unroll
    for (int h = 0; h < HEADS; h++) { m[h] = -1e30f; ssum[h] = 0.f; srl[h] = 0.f; }
    for (int e = beg + tid; e < end; e += 128) {
        int sp = csrc[e] * HEADS;
        int tp = ctype[e] * HEADS;
#pragma unroll
        for (int h = 0; h < HEADS; h++) {
            float rp = s_rp[tp + h];
            float l = a_s[sp + h] + ad[h] + rp;
            l = (l > 0.f) ? l : 0.2f * l;
            srl[h] += rp;
            if (l > m[h]) { ssum[h] = ssum[h] * __expf(m[h] - l) + 1.f; m[h] = l; }
            else          { ssum[h] += __expf(l - m[h]); }
        }
    }
#pragma unroll
    for (int h = 0; h < HEADS; h++) {
        red_m[tid * HEADS + h] = m[h];
        red_s[tid * HEADS + h] = ssum[h];
        red_r[tid * HEADS + h] = srl[h];
    }
    __syncthreads();

    if (tid < HEADS) {
        int h = tid;
        float M = -1e30f, S = 0.f, R = 0.f;
        for (int i = 0; i < 128; i++) {
            float mi = red_m[i * HEADS + h], si = red_s[i * HEADS + h];
            R += red_r[i * HEADS + h];
            if (mi > M) { S = S * __expf(M - mi) + si; M = mi; }
            else        { S += si * __expf(mi - M); }
        }
        float lae = R / (float)max(deg, 1);
        float l = a_s[n * HEADS + h] + ad[h] + lae;
        l = (l > 0.f) ? l : 0.2f * l;
        if (l > M) { S = S * __expf(M - l) + 1.f; M = l; }
        else       { S += __expf(l - M); }
        float inv = 1.f / (S + 1e-16f);
        s_m[h] = M;
        s_inv[h] = inv;
        s_la[h] = __expf(l - M) * inv;
    }
    __syncthreads();

    float mh[HEADS], inv[HEADS];
#pragma unroll
    for (int h = 0; h < HEADS; h++) { mh[h] = s_m[h]; inv[h] = s_inv[h]; }

    // ---- phase B: weighted accumulation. thread tid owns output dim d=tid.
    float acc[HEADS];
    {
        const float* hn = hlin + (long)n * HD + tid;
#pragma unroll
        for (int h = 0; h < HEADS; h++) acc[h] = s_la[h] * hn[h * DH];
    }
    for (int base = beg; base < end; base += 128) {
        int e = base + tid;
        if (e < end) {
            int sp = csrc[e];
            int tp = ctype[e] * HEADS;
            s_src[tid] = sp;
#pragma unroll
            for (int h = 0; h < HEADS; h++) {
                float l = a_s[sp * HEADS + h] + ad[h] + s_rp[tp + h];
                l = (l > 0.f) ? l : 0.2f * l;
                s_alpha[tid * HEADS + h] = __expf(l - mh[h]) * inv[h];
            }
        }
        __syncthreads();
        int cn = min(128, end - base);
        for (int j = 0; j < cn; j++) {
            const float* hs = hlin + (long)s_src[j] * HD + tid;
            float a0 = s_alpha[j * HEADS + 0];
            float a1 = s_alpha[j * HEADS + 1];
            float a2 = s_alpha[j * HEADS + 2];
            float a3 = s_alpha[j * HEADS + 3];
            acc[0] += a0 * hs[0 * DH];
            acc[1] += a1 * hs[1 * DH];
            acc[2] += a2 * hs[2 * DH];
            acc[3] += a3 * hs[3 * DH];
        }
        __syncthreads();
    }
    float o = 0.25f * (acc[0] + acc[1] + acc[2] + acc[3]) + bias[tid];
    o = fmaxf(o, 0.f);   // both GAT layers are followed by relu
    out[(long)n * DH + tid] = o;
}

// ---------------- launch ------------------------------------------------------
extern "C" void kernel_launch(void* const* d_in, const int* in_sizes, int n_in,
                              void* d_out, int out_size) {
    const float* x     = (const float*)d_in[0];
    const int*   eidx  = (const int*)d_in[1];
    const int*   etype = (const int*)d_in[2];
    const float* w1    = (const float*)d_in[3];
    const float* b1    = (const float*)d_in[4];
    const float* w2    = (const float*)d_in[5];
    const float* b2    = (const float*)d_in[6];
    const float* rel   = (const float*)d_in[7];
    const float* lin1  = (const float*)d_in[8];
    const float* line1 = (const float*)d_in[9];
    const float* atts1 = (const float*)d_in[10];
    const float* attd1 = (const float*)d_in[11];
    const float* atte1 = (const float*)d_in[12];
    const float* bias1 = (const float*)d_in[13];
    const float* lin2  = (const float*)d_in[14];
    const float* line2 = (const float*)d_in[15];
    const float* atts2 = (const float*)d_in[16];
    const float* attd2 = (const float*)d_in[17];
    const float* atte2 = (const float*)d_in[18];
    const float* bias2 = (const float*)d_in[19];

    const int N = out_size / DH;          // 20000
    const int E = in_sizes[1] / 2;        // 320000
    const int F = in_sizes[3] / 256;      // 518
    const int* src = eidx;
    const int* dst = eidx + E;

    float *hidden, *h0, *h1, *hlin, *as_, *ad_, *relproj;
    int *cnt, *ctr, *rowptr, *csrc, *ctype;
    cudaGetSymbolAddress((void**)&hidden, g_hidden);
    cudaGetSymbolAddress((void**)&h0, g_h0);
    cudaGetSymbolAddress((void**)&h1, g_h1);
    cudaGetSymbolAddress((void**)&hlin, g_hlin);
    cudaGetSymbolAddress((void**)&as_, g_as);
    cudaGetSymbolAddress((void**)&ad_, g_ad);
    cudaGetSymbolAddress((void**)&cnt, g_cnt);
    cudaGetSymbolAddress((void**)&ctr, g_ctr);
    cudaGetSymbolAddress((void**)&rowptr, g_rowptr);
    cudaGetSymbolAddress((void**)&csrc, g_csrc);
    cudaGetSymbolAddress((void**)&ctype, g_ctype);
    cudaGetSymbolAddress((void**)&relproj, g_relproj);

    // CSR build (same for both layers)
    zero2_kernel<<<(N + 255) / 256, 256>>>(cnt, ctr, N);
    hist_kernel<<<(E + 255) / 256, 256>>>(dst, E, cnt);
    scan_kernel<<<1, 1024>>>(cnt, rowptr, N);
    scatter_kernel<<<(E + 255) / 256, 256>>>(src, dst, etype, E, rowptr, ctr, csrc, ctype);

    // collapsed edge-attention tables
    relproj_kernel<<<1, 128>>>(rel, line1, atte1, relproj);
    relproj_kernel<<<1, 128>>>(rel, line2, atte2, relproj + 26 * HEADS);

    const int MB = (N + 127) / 128;

    // node encoder
    {
        dim3 g(256 / 128, MB);
        mma_gemm<true, true><<<g, 256>>>(N, 256, F, x, w1, b1, hidden);
    }
    {
        dim3 g(1, MB);
        mma_gemm<false, true><<<g, 256>>>(N, DH, 256, hidden, w2, b2, h0);
    }

    // GAT layer 1
    {
        dim3 g(HD / 128, MB);
        mma_gemm<false, false><<<g, 256>>>(N, HD, DH, h0, lin1, nullptr, hlin);
    }
    attdot_kernel<<<N, 128>>>(hlin, atts1, attd1, as_, ad_);
    gat_agg_kernel<<<N, 128>>>(hlin, as_, ad_, rowptr, csrc, ctype,
                               relproj, bias1, h1);

    // GAT layer 2
    {
        dim3 g(HD / 128, MB);
        mma_gemm<false, false><<<g, 256>>>(N, HD, DH, h1, lin2, nullptr, hlin);
    }
    attdot_kernel<<<N, 128>>>(hlin, atts2, attd2, as_, ad_);
    gat_agg_kernel<<<N, 128>>>(hlin, as_, ad_, rowptr, csrc, ctype,
                               relproj + 26 * HEADS, bias2, (float*)d_out);
}

// round 4
// speedup vs baseline: 2.1400x; 1.3481x over previous
#include <cuda_runtime.h>
#include <cstdint>

// ---------------- problem-size bounds (fixed by the dataset) ----------------
#define NMAX 20000
#define EMAX 320000
#define DH   128     // node embedding dim
#define HEADS 4
#define HD   512     // HEADS * DH
#define CAP  128     // cached edges per node (overflow recomputed)

// ---------------- device scratch (no allocations allowed) -------------------
__device__ float g_hidden[NMAX * 256];   // encoder hidden
__device__ float g_h0[NMAX * DH];        // encoder out
__device__ float g_h1[NMAX * DH];        // layer1 out
__device__ float g_hlin[NMAX * HD];      // h @ lin  (per layer, reused)
__device__ float g_as[NMAX * HEADS];
__device__ float g_ad[NMAX * HEADS];
__device__ int   g_cnt[NMAX];
__device__ int   g_ctr[NMAX];
__device__ int   g_rowptr[NMAX + 1];
__device__ int   g_csrc[EMAX];
__device__ int   g_ctype[EMAX];
__device__ float g_relproj[2 * 26 * HEADS];   // [layer][26][4]

// ---------------- small utility kernels -------------------------------------
__global__ void zero2_kernel(int* a, int* b, int n) {
    int i = blockIdx.x * blockDim.x + threadIdx.x;
    if (i < n) { a[i] = 0; b[i] = 0; }
}

__global__ void hist_kernel(const int* __restrict__ dst, int E, int* __restrict__ cnt) {
    int i = blockIdx.x * blockDim.x + threadIdx.x;
    if (i < E) atomicAdd(&cnt[dst[i]], 1);
}

// single-block exclusive scan of cnt[0..n) -> rowptr[0..n]
__global__ void scan_kernel(const int* __restrict__ cnt, int* __restrict__ rowptr, int n) {
    __shared__ int part[1024];
    int tid = threadIdx.x;
    int chunk = (n + 1023) / 1024;
    int b = tid * chunk;
    int e = min(b + chunk, n);
    int s = 0;
    for (int i = b; i < e; i++) s += cnt[i];
    part[tid] = s;
    __syncthreads();
    for (int off = 1; off < 1024; off <<= 1) {
        int v = (tid >= off) ? part[tid - off] : 0;
        __syncthreads();
        part[tid] += v;
        __syncthreads();
    }
    int run = (tid == 0) ? 0 : part[tid - 1];
    for (int i = b; i < e; i++) { rowptr[i] = run; run += cnt[i]; }
    if (tid == 0) rowptr[n] = part[1023];
}

__global__ void scatter_kernel(const int* __restrict__ src, const int* __restrict__ dst,
                               const int* __restrict__ type, int E,
                               const int* __restrict__ rowptr, int* __restrict__ ctr,
                               int* __restrict__ csrc, int* __restrict__ ctype) {
    int i = blockIdx.x * blockDim.x + threadIdx.x;
    if (i < E) {
        int d = dst[i];
        int p = rowptr[d] + atomicAdd(&ctr[d], 1);
        csrc[p]  = src[i];
        ctype[p] = type[i];
    }
}

// relproj[r][h] = sum_k rel_emb[r,k] * (sum_d line[k, h*128+d] * atte[h,d])
__global__ void relproj_kernel(const float* __restrict__ rel_emb,
                               const float* __restrict__ line,
                               const float* __restrict__ atte,
                               float* __restrict__ relproj) {
    __shared__ float we[32 * HEADS];
    int tid = threadIdx.x;   // 128 threads
    {
        int k = tid >> 2, h = tid & 3;
        float s = 0.f;
        const float* lp = line + k * HD + h * DH;
        const float* ap = atte + h * DH;
        for (int d = 0; d < DH; d++) s += lp[d] * ap[d];
        we[k * HEADS + h] = s;
    }
    __syncthreads();
    if (tid < 26 * HEADS) {
        int r = tid >> 2, h = tid & 3;
        float s = 0.f;
        for (int k = 0; k < 32; k++) s += rel_emb[r * 32 + k] * we[k * HEADS + h];
        relproj[tid] = s;
    }
}

// ---------------- tf32 tensor-core GEMM -------------------------------------
__device__ __forceinline__ uint32_t f2tf32(float f) {
    uint32_t u;
    asm("cvt.rna.tf32.f32 %0, %1;" : "=r"(u) : "f"(f));
    return u;
}

__device__ __forceinline__ void mma_tf32(float c[4], const uint32_t a[4], const uint32_t b[2]) {
    asm volatile(
        "mma.sync.aligned.m16n8k8.row.col.f32.tf32.tf32.f32 "
        "{%0,%1,%2,%3}, {%4,%5,%6,%7}, {%8,%9}, {%0,%1,%2,%3};"
        : "+f"(c[0]), "+f"(c[1]), "+f"(c[2]), "+f"(c[3])
        : "r"(a[0]), "r"(a[1]), "r"(a[2]), "r"(a[3]), "r"(b[0]), "r"(b[1]));
}

template <bool RELU, bool HAS_BIAS>
__global__ __launch_bounds__(256, 2) void mma_gemm(
        int M, int N, int K,
        const float* __restrict__ A, const float* __restrict__ B,
        const float* __restrict__ bias, float* __restrict__ C) {
    constexpr int BM = 128, BN = 128, BK = 32;
    constexpr int AP = 36;    // A smem pitch (floats) -> conflict-free
    constexpr int BP = 136;   // B smem pitch (floats) -> conflict-free
    __shared__ uint32_t As[BM * AP];
    __shared__ uint32_t Bs[BK * BP];

    const int tid  = threadIdx.x;
    const int lane = tid & 31;
    const int warp = tid >> 5;
    const int warpM = warp >> 2;
    const int warpN = warp & 3;
    const int bm = blockIdx.y * BM;
    const int bn = blockIdx.x * BN;
    const int mBase = warpM * 64;
    const int nBase = warpN * 32;
    const int qr = lane >> 2;
    const int qc = lane & 3;

    float acc[4][4][4] = {};

    for (int kt = 0; kt < K; kt += BK) {
#pragma unroll
        for (int i = 0; i < 16; i++) {
            int idx = i * 256 + tid;
            int r = idx >> 5, c = idx & 31;
            int gr = bm + r, gc = kt + c;
            float v = (gr < M && gc < K) ? A[(long)gr * K + gc] : 0.f;
            As[r * AP + c] = f2tf32(v);
        }
#pragma unroll
        for (int i = 0; i < 16; i++) {
            int idx = i * 256 + tid;
            int r = idx >> 7, c = idx & 127;
            int gr = kt + r;
            float v = (gr < K) ? B[(long)gr * N + bn + c] : 0.f;
            Bs[r * BP + c] = f2tf32(v);
        }
        __syncthreads();

#pragma unroll
        for (int ks = 0; ks < 4; ks++) {
            const int k0 = ks * 8 + qc;
            uint32_t af[4][4], bf[4][2];
#pragma unroll
            for (int am = 0; am < 4; am++) {
                int r0 = mBase + am * 16 + qr;
                af[am][0] = As[r0 * AP + k0];
                af[am][1] = As[(r0 + 8) * AP + k0];
                af[am][2] = As[r0 * AP + k0 + 4];
                af[am][3] = As[(r0 + 8) * AP + k0 + 4];
            }
#pragma unroll
            for (int bnn = 0; bnn < 4; bnn++) {
                int c0 = nBase + bnn * 8 + qr;
                bf[bnn][0] = Bs[k0 * BP + c0];
                bf[bnn][1] = Bs[(k0 + 4) * BP + c0];
            }
#pragma unroll
            for (int am = 0; am < 4; am++)
#pragma unroll
                for (int bnn = 0; bnn < 4; bnn++)
                    mma_tf32(acc[am][bnn], af[am], bf[bnn]);
        }
        __syncthreads();
    }

#pragma unroll
    for (int am = 0; am < 4; am++) {
        int r0 = bm + mBase + am * 16 + qr;
#pragma unroll
        for (int bnn = 0; bnn < 4; bnn++) {
            int c0 = bn + nBase + bnn * 8 + 2 * qc;
            float b0 = 0.f, b1 = 0.f;
            if (HAS_BIAS) { b0 = bias[c0]; b1 = bias[c0 + 1]; }
#pragma unroll
            for (int half = 0; half < 2; half++) {
                int gr = r0 + half * 8;
                if (gr >= M) continue;
                float v0 = acc[am][bnn][half * 2 + 0] + b0;
                float v1 = acc[am][bnn][half * 2 + 1] + b1;
                if (RELU) { v0 = fmaxf(v0, 0.f); v1 = fmaxf(v1, 0.f); }
                *reinterpret_cast<float2*>(&C[(long)gr * N + c0]) = make_float2(v0, v1);
            }
        }
    }
}

// ---------------- per-node attention score precompute ------------------------
__global__ void attdot_kernel(const float* __restrict__ hlin,
                              const float* __restrict__ atts,
                              const float* __restrict__ attd,
                              float* __restrict__ as_, float* __restrict__ ad_) {
    int n = blockIdx.x;
    int w = threadIdx.x >> 5, lane = threadIdx.x & 31;
    const float* h = hlin + (long)n * HD + w * DH;
    const float* sp = atts + w * DH;
    const float* dp = attd + w * DH;
    float vs = 0.f, vd = 0.f;
#pragma unroll
    for (int i = lane; i < DH; i += 32) {
        float hv = h[i];
        vs += hv * sp[i];
        vd += hv * dp[i];
    }
#pragma unroll
    for (int off = 16; off > 0; off >>= 1) {
        vs += __shfl_down_sync(0xffffffffu, vs, off);
        vd += __shfl_down_sync(0xffffffffu, vd, off);
    }
    if (lane == 0) {
        as_[n * HEADS + w] = vs;
        ad_[n * HEADS + w] = vd;
    }
}

// ---------------- GAT aggregation: one WARP per destination node -------------
// Lane L owns dims [4L,4L+4) of each head (float4 per head). Head-mean is
// lane-local. Logits cached in smem (CAP per node), softmax via shuffles.
__device__ __forceinline__ float leaky02(float x) {
    return (x > 0.f) ? x : 0.2f * x;
}

__global__ __launch_bounds__(256) void gat_agg_kernel(
        const float* __restrict__ hlin,
        const float* __restrict__ a_s,
        const float* __restrict__ a_d,
        const int* __restrict__ rowptr,
        const int* __restrict__ csrc,
        const int* __restrict__ ctype,
        const float* __restrict__ relproj,
        const float* __restrict__ bias,
        float* __restrict__ out, int N) {
    const int w    = threadIdx.x >> 5;     // warp in block (8)
    const int lane = threadIdx.x & 31;
    const int n    = blockIdx.x * 8 + w;

    __shared__ __align__(16) float s_rp[32 * HEADS];   // relproj table (26 used)
    __shared__ __align__(16) float s_l[8][CAP][HEADS]; // logits -> alphas (16KB)
    __shared__ int s_src[8][CAP];                      // cached src ids (4KB)

    if (threadIdx.x < 26 * HEADS) s_rp[threadIdx.x] = relproj[threadIdx.x];
    __syncthreads();
    if (n >= N) return;

    const int beg = rowptr[n], end = rowptr[n + 1];
    const int deg = end - beg;

    const float4 ad4 = *reinterpret_cast<const float4*>(a_d + n * HEADS);

    // ---- phase A: logits for all incoming edges (lanes parallel) ----
    float m0 = -1e30f, m1 = -1e30f, m2 = -1e30f, m3 = -1e30f;
    float s0 = 0.f, s1 = 0.f, s2 = 0.f, s3 = 0.f;
    float r0 = 0.f, r1 = 0.f, r2 = 0.f, r3 = 0.f;       // sum of relproj (self-loop mean)
    for (int j = lane; j < deg; j += 32) {
        const int e  = beg + j;
        const int sp = csrc[e];
        const int tp = ctype[e];
        const float4 as4 = *reinterpret_cast<const float4*>(a_s + sp * HEADS);
        const float4 rp4 = *reinterpret_cast<const float4*>(s_rp + tp * HEADS);
        float l0 = leaky02(as4.x + ad4.x + rp4.x);
        float l1 = leaky02(as4.y + ad4.y + rp4.y);
        float l2 = leaky02(as4.z + ad4.z + rp4.z);
        float l3 = leaky02(as4.w + ad4.w + rp4.w);
        r0 += rp4.x; r1 += rp4.y; r2 += rp4.z; r3 += rp4.w;
        if (j < CAP) {
            s_src[w][j] = sp;
            *reinterpret_cast<float4*>(s_l[w][j]) = make_float4(l0, l1, l2, l3);
        }
        // online per-lane max/sum
        if (l0 > m0) { s0 = s0 * __expf(m0 - l0) + 1.f; m0 = l0; } else s0 += __expf(l0 - m0);
        if (l1 > m1) { s1 = s1 * __expf(m1 - l1) + 1.f; m1 = l1; } else s1 += __expf(l1 - m1);
        if (l2 > m2) { s2 = s2 * __expf(m2 - l2) + 1.f; m2 = l2; } else s2 += __expf(l2 - m2);
        if (l3 > m3) { s3 = s3 * __expf(m3 - l3) + 1.f; m3 = l3; } else s3 += __expf(l3 - m3);
    }
    // cross-lane merge (butterfly): all lanes end with global (m,S), and summed r
#pragma unroll
    for (int off = 16; off > 0; off >>= 1) {
        float mo, so;
        mo = __shfl_xor_sync(~0u, m0, off); so = __shfl_xor_sync(~0u, s0, off);
        if (mo > m0) { s0 = s0 * __expf(m0 - mo) + so; m0 = mo; } else s0 += so * __expf(mo - m0);
        mo = __shfl_xor_sync(~0u, m1, off); so = __shfl_xor_sync(~0u, s1, off);
        if (mo > m1) { s1 = s1 * __expf(m1 - mo) + so; m1 = mo; } else s1 += so * __expf(mo - m1);
        mo = __shfl_xor_sync(~0u, m2, off); so = __shfl_xor_sync(~0u, s2, off);
        if (mo > m2) { s2 = s2 * __expf(m2 - mo) + so; m2 = mo; } else s2 += so * __expf(mo - m2);
        mo = __shfl_xor_sync(~0u, m3, off); so = __shfl_xor_sync(~0u, s3, off);
        if (mo > m3) { s3 = s3 * __expf(m3 - mo) + so; m3 = mo; } else s3 += so * __expf(mo - m3);
        r0 += __shfl_xor_sync(~0u, r0, off);
        r1 += __shfl_xor_sync(~0u, r1, off);
        r2 += __shfl_xor_sync(~0u, r2, off);
        r3 += __shfl_xor_sync(~0u, r3, off);
    }

    // self loop: a_e = mean of relproj over incoming edges
    const float4 asn = *reinterpret_cast<const float4*>(a_s + n * HEADS);
    const float dinv = 1.f / (float)max(deg, 1);
    float ls0 = leaky02(asn.x + ad4.x + r0 * dinv);
    float ls1 = leaky02(asn.y + ad4.y + r1 * dinv);
    float ls2 = leaky02(asn.z + ad4.z + r2 * dinv);
    float ls3 = leaky02(asn.w + ad4.w + r3 * dinv);
    if (ls0 > m0) { s0 = s0 * __expf(m0 - ls0) + 1.f; m0 = ls0; } else s0 += __expf(ls0 - m0);
    if (ls1 > m1) { s1 = s1 * __expf(m1 - ls1) + 1.f; m1 = ls1; } else s1 += __expf(ls1 - m1);
    if (ls2 > m2) { s2 = s2 * __expf(m2 - ls2) + 1.f; m2 = ls2; } else s2 += __expf(ls2 - m2);
    if (ls3 > m3) { s3 = s3 * __expf(m3 - ls3) + 1.f; m3 = ls3; } else s3 += __expf(ls3 - m3);
    const float i0 = 1.f / (s0 + 1e-16f), i1 = 1.f / (s1 + 1e-16f);
    const float i2 = 1.f / (s2 + 1e-16f), i3 = 1.f / (s3 + 1e-16f);
    const float la0 = __expf(ls0 - m0) * i0, la1 = __expf(ls1 - m1) * i1;
    const float la2 = __expf(ls2 - m2) * i2, la3 = __expf(ls3 - m3) * i3;

    __syncwarp();
    // convert cached logits -> alphas in place
    const int ncached = min(deg, CAP);
    for (int j = lane; j < ncached; j += 32) {
        float4 l4 = *reinterpret_cast<float4*>(s_l[w][j]);
        l4.x = __expf(l4.x - m0) * i0;
        l4.y = __expf(l4.y - m1) * i1;
        l4.z = __expf(l4.z - m2) * i2;
        l4.w = __expf(l4.w - m3) * i3;
        *reinterpret_cast<float4*>(s_l[w][j]) = l4;
    }
    __syncwarp();

    // ---- phase B: weighted accumulation, lane L -> dims [4L,4L+4) per head.
    const float4* hn = reinterpret_cast<const float4*>(hlin + (long)n * HD) + lane;
    float4 a0, a1, a2, a3;
    {
        float4 v;
        v = hn[0];  a0 = make_float4(la0 * v.x, la0 * v.y, la0 * v.z, la0 * v.w);
        v = hn[32]; a1 = make_float4(la1 * v.x, la1 * v.y, la1 * v.z, la1 * v.w);
        v = hn[64]; a2 = make_float4(la2 * v.x, la2 * v.y, la2 * v.z, la2 * v.w);
        v = hn[96]; a3 = make_float4(la3 * v.x, la3 * v.y, la3 * v.z, la3 * v.w);
    }
#pragma unroll 2
    for (int j = 0; j < deg; j++) {
        int sp; float4 al;
        if (j < CAP) {
            sp = s_src[w][j];
            al = *reinterpret_cast<const float4*>(s_l[w][j]);
        } else {                      // overflow path (deg > CAP): recompute
            const int e  = beg + j;
            sp = csrc[e];
            const int tp = ctype[e];
            const float4 as4 = *reinterpret_cast<const float4*>(a_s + sp * HEADS);
            const float4 rp4 = *reinterpret_cast<const float4*>(s_rp + tp * HEADS);
            al.x = __expf(leaky02(as4.x + ad4.x + rp4.x) - m0) * i0;
            al.y = __expf(leaky02(as4.y + ad4.y + rp4.y) - m1) * i1;
            al.z = __expf(leaky02(as4.z + ad4.z + rp4.z) - m2) * i2;
            al.w = __expf(leaky02(as4.w + ad4.w + rp4.w) - m3) * i3;
        }
        const float4* hs = reinterpret_cast<const float4*>(hlin + (long)sp * HD) + lane;
        float4 v;
        v = hs[0];
        a0.x += al.x * v.x; a0.y += al.x * v.y; a0.z += al.x * v.z; a0.w += al.x * v.w;
        v = hs[32];
        a1.x += al.y * v.x; a1.y += al.y * v.y; a1.z += al.y * v.z; a1.w += al.y * v.w;
        v = hs[64];
        a2.x += al.z * v.x; a2.y += al.z * v.y; a2.z += al.z * v.z; a2.w += al.z * v.w;
        v = hs[96];
        a3.x += al.w * v.x; a3.y += al.w * v.y; a3.z += al.w * v.z; a3.w += al.w * v.w;
    }

    const float4 b4 = *reinterpret_cast<const float4*>(bias + 4 * lane);
    float4 o;
    o.x = fmaxf(0.25f * (a0.x + a1.x + a2.x + a3.x) + b4.x, 0.f);
    o.y = fmaxf(0.25f * (a0.y + a1.y + a2.y + a3.y) + b4.y, 0.f);
    o.z = fmaxf(0.25f * (a0.z + a1.z + a2.z + a3.z) + b4.z, 0.f);
    o.w = fmaxf(0.25f * (a0.w + a1.w + a2.w + a3.w) + b4.w, 0.f);
    *reinterpret_cast<float4*>(out + (long)n * DH + 4 * lane) = o;
}

// ---------------- launch ------------------------------------------------------
extern "C" void kernel_launch(void* const* d_in, const int* in_sizes, int n_in,
                              void* d_out, int out_size) {
    const float* x     = (const float*)d_in[0];
    const int*   eidx  = (const int*)d_in[1];
    const int*   etype = (const int*)d_in[2];
    const float* w1    = (const float*)d_in[3];
    const float* b1    = (const float*)d_in[4];
    const float* w2    = (const float*)d_in[5];
    const float* b2    = (const float*)d_in[6];
    const float* rel   = (const float*)d_in[7];
    const float* lin1  = (const float*)d_in[8];
    const float* line1 = (const float*)d_in[9];
    const float* atts1 = (const float*)d_in[10];
    const float* attd1 = (const float*)d_in[11];
    const float* atte1 = (const float*)d_in[12];
    const float* bias1 = (const float*)d_in[13];
    const float* lin2  = (const float*)d_in[14];
    const float* line2 = (const float*)d_in[15];
    const float* atts2 = (const float*)d_in[16];
    const float* attd2 = (const float*)d_in[17];
    const float* atte2 = (const float*)d_in[18];
    const float* bias2 = (const float*)d_in[19];

    const int N = out_size / DH;          // 20000
    const int E = in_sizes[1] / 2;        // 320000
    const int F = in_sizes[3] / 256;      // 518
    const int* src = eidx;
    const int* dst = eidx + E;

    float *hidden, *h0, *h1, *hlin, *as_, *ad_, *relproj;
    int *cnt, *ctr, *rowptr, *csrc, *ctype;
    cudaGetSymbolAddress((void**)&hidden, g_hidden);
    cudaGetSymbolAddress((void**)&h0, g_h0);
    cudaGetSymbolAddress((void**)&h1, g_h1);
    cudaGetSymbolAddress((void**)&hlin, g_hlin);
    cudaGetSymbolAddress((void**)&as_, g_as);
    cudaGetSymbolAddress((void**)&ad_, g_ad);
    cudaGetSymbolAddress((void**)&cnt, g_cnt);
    cudaGetSymbolAddress((void**)&ctr, g_ctr);
    cudaGetSymbolAddress((void**)&rowptr, g_rowptr);
    cudaGetSymbolAddress((void**)&csrc, g_csrc);
    cudaGetSymbolAddress((void**)&ctype, g_ctype);
    cudaGetSymbolAddress((void**)&relproj, g_relproj);

    // CSR build (same for both layers)
    zero2_kernel<<<(N + 255) / 256, 256>>>(cnt, ctr, N);
    hist_kernel<<<(E + 255) / 256, 256>>>(dst, E, cnt);
    scan_kernel<<<1, 1024>>>(cnt, rowptr, N);
    scatter_kernel<<<(E + 255) / 256, 256>>>(src, dst, etype, E, rowptr, ctr, csrc, ctype);

    // collapsed edge-attention tables
    relproj_kernel<<<1, 128>>>(rel, line1, atte1, relproj);
    relproj_kernel<<<1, 128>>>(rel, line2, atte2, relproj + 26 * HEADS);

    const int MB = (N + 127) / 128;
    const int AGG_B = (N + 7) / 8;

    // node encoder
    {
        dim3 g(256 / 128, MB);
        mma_gemm<true, true><<<g, 256>>>(N, 256, F, x, w1, b1, hidden);
    }
    {
        dim3 g(1, MB);
        mma_gemm<false, true><<<g, 256>>>(N, DH, 256, hidden, w2, b2, h0);
    }

    // GAT layer 1
    {
        dim3 g(HD / 128, MB);
        mma_gemm<false, false><<<g, 256>>>(N, HD, DH, h0, lin1, nullptr, hlin);
    }
    attdot_kernel<<<N, 128>>>(hlin, atts1, attd1, as_, ad_);
    gat_agg_kernel<<<AGG_B, 256>>>(hlin, as_, ad_, rowptr, csrc, ctype,
                                   relproj, bias1, h1, N);

    // GAT layer 2
    {
        dim3 g(HD / 128, MB);
        mma_gemm<false, false><<<g, 256>>>(N, HD, DH, h1, lin2, nullptr, hlin);
    }
    attdot_kernel<<<N, 128>>>(hlin, atts2, attd2, as_, ad_);
    gat_agg_kernel<<<AGG_B, 256>>>(hlin, as_, ad_, rowptr, csrc, ctype,
                                   relproj + 26 * HEADS, bias2, (float*)d_out, N);
}

// round 5
// speedup vs baseline: 2.4552x; 1.1473x over previous
#include <cuda_runtime.h>
#include <cstdint>

// ---------------- problem-size bounds (fixed by the dataset) ----------------
#define NMAX 20000
#define EMAX 320000
#define DH   128     // node embedding dim
#define HEADS 4
#define HD   512     // HEADS * DH
#define CAP  128     // cached edges per node (overflow recomputed)

// ---------------- device scratch (no allocations allowed) -------------------
__device__ float g_hidden[NMAX * 256];   // encoder hidden
__device__ float g_h0[NMAX * DH];        // encoder out
__device__ float g_h1[NMAX * DH];        // layer1 out
__device__ float g_hlin[NMAX * HD];      // h @ lin  (per layer, reused)
__device__ float g_as[NMAX * HEADS];
__device__ float g_ad[NMAX * HEADS];
__device__ int   g_cnt[NMAX];
__device__ int   g_ctr[NMAX];
__device__ int   g_rowptr[NMAX + 1];
__device__ int   g_csrc[EMAX];
__device__ int   g_ctype[EMAX];
__device__ float g_relproj[2 * 26 * HEADS];   // [layer][26][4]

// ---------------- small utility kernels -------------------------------------
__global__ void zero2_kernel(int* a, int* b, int n) {
    int i = blockIdx.x * blockDim.x + threadIdx.x;
    if (i < n) { a[i] = 0; b[i] = 0; }
}

__global__ void zeroatt_kernel(float* a, float* b, int n) {
    int i = blockIdx.x * blockDim.x + threadIdx.x;
    if (i < n) { a[i] = 0.f; b[i] = 0.f; }
}

__global__ void hist_kernel(const int* __restrict__ dst, int E, int* __restrict__ cnt) {
    int i = blockIdx.x * blockDim.x + threadIdx.x;
    if (i < E) atomicAdd(&cnt[dst[i]], 1);
}

// single-block exclusive scan of cnt[0..n) -> rowptr[0..n]
__global__ void scan_kernel(const int* __restrict__ cnt, int* __restrict__ rowptr, int n) {
    __shared__ int part[1024];
    int tid = threadIdx.x;
    int chunk = (n + 1023) / 1024;
    int b = tid * chunk;
    int e = min(b + chunk, n);
    int s = 0;
    for (int i = b; i < e; i++) s += cnt[i];
    part[tid] = s;
    __syncthreads();
    for (int off = 1; off < 1024; off <<= 1) {
        int v = (tid >= off) ? part[tid - off] : 0;
        __syncthreads();
        part[tid] += v;
        __syncthreads();
    }
    int run = (tid == 0) ? 0 : part[tid - 1];
    for (int i = b; i < e; i++) { rowptr[i] = run; run += cnt[i]; }
    if (tid == 0) rowptr[n] = part[1023];
}

__global__ void scatter_kernel(const int* __restrict__ src, const int* __restrict__ dst,
                               const int* __restrict__ type, int E,
                               const int* __restrict__ rowptr, int* __restrict__ ctr,
                               int* __restrict__ csrc, int* __restrict__ ctype) {
    int i = blockIdx.x * blockDim.x + threadIdx.x;
    if (i < E) {
        int d = dst[i];
        int p = rowptr[d] + atomicAdd(&ctr[d], 1);
        csrc[p]  = src[i];
        ctype[p] = type[i];
    }
}

// relproj[r][h] = sum_k rel_emb[r,k] * (sum_d line[k, h*128+d] * atte[h,d])
__global__ void relproj_kernel(const float* __restrict__ rel_emb,
                               const float* __restrict__ line,
                               const float* __restrict__ atte,
                               float* __restrict__ relproj) {
    __shared__ float we[32 * HEADS];
    int tid = threadIdx.x;   // 128 threads
    {
        int k = tid >> 2, h = tid & 3;
        float s = 0.f;
        const float* lp = line + k * HD + h * DH;
        const float* ap = atte + h * DH;
        for (int d = 0; d < DH; d++) s += lp[d] * ap[d];
        we[k * HEADS + h] = s;
    }
    __syncthreads();
    if (tid < 26 * HEADS) {
        int r = tid >> 2, h = tid & 3;
        float s = 0.f;
        for (int k = 0; k < 32; k++) s += rel_emb[r * 32 + k] * we[k * HEADS + h];
        relproj[tid] = s;
    }
}

// ---------------- tf32 tensor-core GEMM (cp.async 2-stage) -------------------
__device__ __forceinline__ uint32_t f2tf32(float f) {
    uint32_t u;
    asm("cvt.rna.tf32.f32 %0, %1;" : "=r"(u) : "f"(f));
    return u;
}

__device__ __forceinline__ void mma_tf32(float c[4], const uint32_t a[4], const uint32_t b[2]) {
    asm volatile(
        "mma.sync.aligned.m16n8k8.row.col.f32.tf32.tf32.f32 "
        "{%0,%1,%2,%3}, {%4,%5,%6,%7}, {%8,%9}, {%0,%1,%2,%3};"
        : "+f"(c[0]), "+f"(c[1]), "+f"(c[2]), "+f"(c[3])
        : "r"(a[0]), "r"(a[1]), "r"(a[2]), "r"(a[3]), "r"(b[0]), "r"(b[1]));
}

__device__ __forceinline__ void cp4(uint32_t smem_u32, const float* gptr, bool pred) {
    int sz = pred ? 4 : 0;
    asm volatile("cp.async.ca.shared.global [%0], [%1], 4, %2;"
                 :: "r"(smem_u32), "l"(gptr), "r"(sz));
}
__device__ __forceinline__ void cp_commit() {
    asm volatile("cp.async.commit_group;");
}
__device__ __forceinline__ void cp_wait0() {
    asm volatile("cp.async.wait_group 0;");
}

// C = act(A[M,K] @ B[K,N] + bias). BM=128 BN=128 BK=16, 8 warps (2m x 4n),
// warp tile 64x32 = 4x4 m16n8k8 atoms. Two cp.async stages.
// If ATT: BN==DH and blockIdx.x is the head; accumulate per-row attention dots
// (acc . atts_h, acc . attd_h) into as_/ad_ via atomics (arrays pre-zeroed).
template <bool RELU, bool HAS_BIAS, bool ATT>
__global__ __launch_bounds__(256, 2) void mma_gemm(
        int M, int N, int K,
        const float* __restrict__ A, const float* __restrict__ B,
        const float* __restrict__ bias, float* __restrict__ C,
        const float* __restrict__ atts, const float* __restrict__ attd,
        float* __restrict__ as_, float* __restrict__ ad_) {
    constexpr int BM = 128, BN = 128, BK = 16;
    constexpr int AP = 20;    // A smem pitch: frag banks 20*qr+qc -> all 32 distinct
    constexpr int BP = 136;   // B smem pitch: frag banks 8*qc+qr -> all 32 distinct
    __shared__ float As[2][BM * AP];
    __shared__ float Bs[2][BK * BP];

    const int tid  = threadIdx.x;
    const int lane = tid & 31;
    const int warp = tid >> 5;
    const int warpM = warp >> 2;
    const int warpN = warp & 3;
    const int bm = blockIdx.y * BM;
    const int bn = blockIdx.x * BN;
    const int mBase = warpM * 64;
    const int nBase = warpN * 32;
    const int qr = lane >> 2;
    const int qc = lane & 3;

    const uint32_t sA0 = (uint32_t)__cvta_generic_to_shared(&As[0][0]);
    const uint32_t sA1 = (uint32_t)__cvta_generic_to_shared(&As[1][0]);
    const uint32_t sB0 = (uint32_t)__cvta_generic_to_shared(&Bs[0][0]);
    const uint32_t sB1 = (uint32_t)__cvta_generic_to_shared(&Bs[1][0]);

    // per-thread load coordinates
    const int ar = tid >> 1;                 // wrong granularity? recompute below
    (void)ar;

    float acc[4][4][4] = {};

    // issue loads for k-tile kt into stage s
    auto issue = [&](int kt, int s) {
        const uint32_t aBase = s ? sA1 : sA0;
        const uint32_t bBase = s ? sB1 : sB0;
#pragma unroll
        for (int i = 0; i < 8; i++) {        // A: 128x16 = 2048 / 256 = 8
            int idx = i * 256 + tid;
            int r = idx >> 4, c = idx & 15;
            int gr = bm + r, gc = kt + c;
            cp4(aBase + (uint32_t)(r * AP + c) * 4,
                A + (long)gr * K + gc, (gr < M) && (gc < K));
        }
#pragma unroll
        for (int i = 0; i < 8; i++) {        // B: 16x128 = 2048 / 256 = 8
            int idx = i * 256 + tid;
            int r = idx >> 7, c = idx & 127;
            int gr = kt + r;
            cp4(bBase + (uint32_t)(r * BP + c) * 4,
                B + (long)gr * N + bn + c, gr < K);
        }
        cp_commit();
    };

    issue(0, 0);
    const int nkt = (K + BK - 1) / BK;
    int s = 0;
    for (int it = 0; it < nkt; it++, s ^= 1) {
        cp_wait0();
        __syncthreads();
        if (it + 1 < nkt) issue((it + 1) * BK, s ^ 1);

        const float* Acur = As[s];
        const float* Bcur = Bs[s];
#pragma unroll
        for (int ks = 0; ks < 2; ks++) {
            const int k0 = ks * 8 + qc;
            uint32_t af[4][4], bf[4][2];
#pragma unroll
            for (int am = 0; am < 4; am++) {
                int r0 = mBase + am * 16 + qr;
                af[am][0] = f2tf32(Acur[r0 * AP + k0]);
                af[am][1] = f2tf32(Acur[(r0 + 8) * AP + k0]);
                af[am][2] = f2tf32(Acur[r0 * AP + k0 + 4]);
                af[am][3] = f2tf32(Acur[(r0 + 8) * AP + k0 + 4]);
            }
#pragma unroll
            for (int bnn = 0; bnn < 4; bnn++) {
                int c0 = nBase + bnn * 8 + qr;
                bf[bnn][0] = f2tf32(Bcur[k0 * BP + c0]);
                bf[bnn][1] = f2tf32(Bcur[(k0 + 4) * BP + c0]);
            }
#pragma unroll
            for (int am = 0; am < 4; am++)
#pragma unroll
                for (int bnn = 0; bnn < 4; bnn++)
                    mma_tf32(acc[am][bnn], af[am], bf[bnn]);
        }
        __syncthreads();
    }

    // ---- epilogue: C store (+ optional fused attention dots) ----
#pragma unroll
    for (int am = 0; am < 4; am++) {
        int r0 = bm + mBase + am * 16 + qr;
#pragma unroll
        for (int bnn = 0; bnn < 4; bnn++) {
            int c0 = bn + nBase + bnn * 8 + 2 * qc;
            float b0 = 0.f, b1 = 0.f;
            if (HAS_BIAS) { b0 = bias[c0]; b1 = bias[c0 + 1]; }
#pragma unroll
            for (int half = 0; half < 2; half++) {
                int gr = r0 + half * 8;
                if (gr >= M) continue;
                float v0 = acc[am][bnn][half * 2 + 0] + b0;
                float v1 = acc[am][bnn][half * 2 + 1] + b1;
                if (RELU) { v0 = fmaxf(v0, 0.f); v1 = fmaxf(v1, 0.f); }
                *reinterpret_cast<float2*>(&C[(long)gr * N + c0]) = make_float2(v0, v1);
            }
        }
    }

    if (ATT) {
        const int hh = blockIdx.x;                   // head (BN==DH==128)
        float w0s[4], w1s[4], w0d[4], w1d[4];
#pragma unroll
        for (int bnn = 0; bnn < 4; bnn++) {
            int cl = nBase + bnn * 8 + 2 * qc;       // local col 0..127
            w0s[bnn] = atts[hh * DH + cl];  w1s[bnn] = atts[hh * DH + cl + 1];
            w0d[bnn] = attd[hh * DH + cl];  w1d[bnn] = attd[hh * DH + cl + 1];
        }
        float ps[4][2], pd[4][2];
#pragma unroll
        for (int am = 0; am < 4; am++)
#pragma unroll
            for (int half = 0; half < 2; half++) {
                float s_ = 0.f, d_ = 0.f;
#pragma unroll
                for (int bnn = 0; bnn < 4; bnn++) {
                    float v0 = acc[am][bnn][half * 2 + 0];
                    float v1 = acc[am][bnn][half * 2 + 1];
                    s_ += v0 * w0s[bnn] + v1 * w1s[bnn];
                    d_ += v0 * w0d[bnn] + v1 * w1d[bnn];
                }
                ps[am][half] = s_; pd[am][half] = d_;
            }
        // reduce over qc lanes (bits 0..1 of lane)
#pragma unroll
        for (int off = 1; off <= 2; off <<= 1)
#pragma unroll
            for (int am = 0; am < 4; am++)
#pragma unroll
                for (int half = 0; half < 2; half++) {
                    ps[am][half] += __shfl_xor_sync(~0u, ps[am][half], off);
                    pd[am][half] += __shfl_xor_sync(~0u, pd[am][half], off);
                }
        if (qc == 0) {
#pragma unroll
            for (int am = 0; am < 4; am++)
#pragma unroll
                for (int half = 0; half < 2; half++) {
                    int gr = bm + mBase + am * 16 + qr + half * 8;
                    if (gr < M) {
                        atomicAdd(&as_[gr * HEADS + hh], ps[am][half]);
                        atomicAdd(&ad_[gr * HEADS + hh], pd[am][half]);
                    }
                }
        }
    }
}

// ---------------- GAT aggregation: one WARP per destination node -------------
__device__ __forceinline__ float leaky02(float x) {
    return (x > 0.f) ? x : 0.2f * x;
}

__global__ __launch_bounds__(256) void gat_agg_kernel(
        const float* __restrict__ hlin,
        const float* __restrict__ a_s,
        const float* __restrict__ a_d,
        const int* __restrict__ rowptr,
        const int* __restrict__ csrc,
        const int* __restrict__ ctype,
        const float* __restrict__ relproj,
        const float* __restrict__ bias,
        float* __restrict__ out, int N) {
    const int w    = threadIdx.x >> 5;     // warp in block (8)
    const int lane = threadIdx.x & 31;
    const int n    = blockIdx.x * 8 + w;

    __shared__ __align__(16) float s_rp[32 * HEADS];   // relproj table (26 used)
    __shared__ __align__(16) float s_l[8][CAP][HEADS]; // logits -> alphas (16KB)
    __shared__ int s_src[8][CAP];                      // cached src ids (4KB)

    if (threadIdx.x < 26 * HEADS) s_rp[threadIdx.x] = relproj[threadIdx.x];
    __syncthreads();
    if (n >= N) return;

    const int beg = rowptr[n], end = rowptr[n + 1];
    const int deg = end - beg;

    const float4 ad4 = *reinterpret_cast<const float4*>(a_d + n * HEADS);

    // ---- phase A: logits for all incoming edges (lanes parallel) ----
    float m0 = -1e30f, m1 = -1e30f, m2 = -1e30f, m3 = -1e30f;
    float s0 = 0.f, s1 = 0.f, s2 = 0.f, s3 = 0.f;
    float r0 = 0.f, r1 = 0.f, r2 = 0.f, r3 = 0.f;       // sum of relproj (self-loop mean)
    for (int j = lane; j < deg; j += 32) {
        const int e  = beg + j;
        const int sp = csrc[e];
        const int tp = ctype[e];
        const float4 as4 = *reinterpret_cast<const float4*>(a_s + sp * HEADS);
        const float4 rp4 = *reinterpret_cast<const float4*>(s_rp + tp * HEADS);
        float l0 = leaky02(as4.x + ad4.x + rp4.x);
        float l1 = leaky02(as4.y + ad4.y + rp4.y);
        float l2 = leaky02(as4.z + ad4.z + rp4.z);
        float l3 = leaky02(as4.w + ad4.w + rp4.w);
        r0 += rp4.x; r1 += rp4.y; r2 += rp4.z; r3 += rp4.w;
        if (j < CAP) {
            s_src[w][j] = sp;
            *reinterpret_cast<float4*>(s_l[w][j]) = make_float4(l0, l1, l2, l3);
        }
        if (l0 > m0) { s0 = s0 * __expf(m0 - l0) + 1.f; m0 = l0; } else s0 += __expf(l0 - m0);
        if (l1 > m1) { s1 = s1 * __expf(m1 - l1) + 1.f; m1 = l1; } else s1 += __expf(l1 - m1);
        if (l2 > m2) { s2 = s2 * __expf(m2 - l2) + 1.f; m2 = l2; } else s2 += __expf(l2 - m2);
        if (l3 > m3) { s3 = s3 * __expf(m3 - l3) + 1.f; m3 = l3; } else s3 += __expf(l3 - m3);
    }
#pragma unroll
    for (int off = 16; off > 0; off >>= 1) {
        float mo, so;
        mo = __shfl_xor_sync(~0u, m0, off); so = __shfl_xor_sync(~0u, s0, off);
        if (mo > m0) { s0 = s0 * __expf(m0 - mo) + so; m0 = mo; } else s0 += so * __expf(mo - m0);
        mo = __shfl_xor_sync(~0u, m1, off); so = __shfl_xor_sync(~0u, s1, off);
        if (mo > m1) { s1 = s1 * __expf(m1 - mo) + so; m1 = mo; } else s1 += so * __expf(mo - m1);
        mo = __shfl_xor_sync(~0u, m2, off); so = __shfl_xor_sync(~0u, s2, off);
        if (mo > m2) { s2 = s2 * __expf(m2 - mo) + so; m2 = mo; } else s2 += so * __expf(mo - m2);
        mo = __shfl_xor_sync(~0u, m3, off); so = __shfl_xor_sync(~0u, s3, off);
        if (mo > m3) { s3 = s3 * __expf(m3 - mo) + so; m3 = mo; } else s3 += so * __expf(mo - m3);
        r0 += __shfl_xor_sync(~0u, r0, off);
        r1 += __shfl_xor_sync(~0u, r1, off);
        r2 += __shfl_xor_sync(~0u, r2, off);
        r3 += __shfl_xor_sync(~0u, r3, off);
    }

    // self loop: a_e = mean of relproj over incoming edges
    const float4 asn = *reinterpret_cast<const float4*>(a_s + n * HEADS);
    const float dinv = 1.f / (float)max(deg, 1);
    float ls0 = leaky02(asn.x + ad4.x + r0 * dinv);
    float ls1 = leaky02(asn.y + ad4.y + r1 * dinv);
    float ls2 = leaky02(asn.z + ad4.z + r2 * dinv);
    float ls3 = leaky02(asn.w + ad4.w + r3 * dinv);
    if (ls0 > m0) { s0 = s0 * __expf(m0 - ls0) + 1.f; m0 = ls0; } else s0 += __expf(ls0 - m0);
    if (ls1 > m1) { s1 = s1 * __expf(m1 - ls1) + 1.f; m1 = ls1; } else s1 += __expf(ls1 - m1);
    if (ls2 > m2) { s2 = s2 * __expf(m2 - ls2) + 1.f; m2 = ls2; } else s2 += __expf(ls2 - m2);
    if (ls3 > m3) { s3 = s3 * __expf(m3 - ls3) + 1.f; m3 = ls3; } else s3 += __expf(ls3 - m3);
    const float i0 = 1.f / (s0 + 1e-16f), i1 = 1.f / (s1 + 1e-16f);
    const float i2 = 1.f / (s2 + 1e-16f), i3 = 1.f / (s3 + 1e-16f);
    const float la0 = __expf(ls0 - m0) * i0, la1 = __expf(ls1 - m1) * i1;
    const float la2 = __expf(ls2 - m2) * i2, la3 = __expf(ls3 - m3) * i3;

    __syncwarp();
    const int ncached = min(deg, CAP);
    for (int j = lane; j < ncached; j += 32) {
        float4 l4 = *reinterpret_cast<float4*>(s_l[w][j]);
        l4.x = __expf(l4.x - m0) * i0;
        l4.y = __expf(l4.y - m1) * i1;
        l4.z = __expf(l4.z - m2) * i2;
        l4.w = __expf(l4.w - m3) * i3;
        *reinterpret_cast<float4*>(s_l[w][j]) = l4;
    }
    __syncwarp();

    // ---- phase B: weighted accumulation, lane L -> dims [4L,4L+4) per head.
    const float4* hn = reinterpret_cast<const float4*>(hlin + (long)n * HD) + lane;
    float4 a0, a1, a2, a3;
    {
        float4 v;
        v = hn[0];  a0 = make_float4(la0 * v.x, la0 * v.y, la0 * v.z, la0 * v.w);
        v = hn[32]; a1 = make_float4(la1 * v.x, la1 * v.y, la1 * v.z, la1 * v.w);
        v = hn[64]; a2 = make_float4(la2 * v.x, la2 * v.y, la2 * v.z, la2 * v.w);
        v = hn[96]; a3 = make_float4(la3 * v.x, la3 * v.y, la3 * v.z, la3 * v.w);
    }
#pragma unroll 2
    for (int j = 0; j < deg; j++) {
        int sp; float4 al;
        if (j < CAP) {
            sp = s_src[w][j];
            al = *reinterpret_cast<const float4*>(s_l[w][j]);
        } else {                      // overflow path (deg > CAP): recompute
            const int e  = beg + j;
            sp = csrc[e];
            const int tp = ctype[e];
            const float4 as4 = *reinterpret_cast<const float4*>(a_s + sp * HEADS);
            const float4 rp4 = *reinterpret_cast<const float4*>(s_rp + tp * HEADS);
            al.x = __expf(leaky02(as4.x + ad4.x + rp4.x) - m0) * i0;
            al.y = __expf(leaky02(as4.y + ad4.y + rp4.y) - m1) * i1;
            al.z = __expf(leaky02(as4.z + ad4.z + rp4.z) - m2) * i2;
            al.w = __expf(leaky02(as4.w + ad4.w + rp4.w) - m3) * i3;
        }
        const float4* hs = reinterpret_cast<const float4*>(hlin + (long)sp * HD) + lane;
        float4 v;
        v = hs[0];
        a0.x += al.x * v.x; a0.y += al.x * v.y; a0.z += al.x * v.z; a0.w += al.x * v.w;
        v = hs[32];
        a1.x += al.y * v.x; a1.y += al.y * v.y; a1.z += al.y * v.z; a1.w += al.y * v.w;
        v = hs[64];
        a2.x += al.z * v.x; a2.y += al.z * v.y; a2.z += al.z * v.z; a2.w += al.z * v.w;
        v = hs[96];
        a3.x += al.w * v.x; a3.y += al.w * v.y; a3.z += al.w * v.z; a3.w += al.w * v.w;
    }

    const float4 b4 = *reinterpret_cast<const float4*>(bias + 4 * lane);
    float4 o;
    o.x = fmaxf(0.25f * (a0.x + a1.x + a2.x + a3.x) + b4.x, 0.f);
    o.y = fmaxf(0.25f * (a0.y + a1.y + a2.y + a3.y) + b4.y, 0.f);
    o.z = fmaxf(0.25f * (a0.z + a1.z + a2.z + a3.z) + b4.z, 0.f);
    o.w = fmaxf(0.25f * (a0.w + a1.w + a2.w + a3.w) + b4.w, 0.f);
    *reinterpret_cast<float4*>(out + (long)n * DH + 4 * lane) = o;
}

// ---------------- launch ------------------------------------------------------
extern "C" void kernel_launch(void* const* d_in, const int* in_sizes, int n_in,
                              void* d_out, int out_size) {
    const float* x     = (const float*)d_in[0];
    const int*   eidx  = (const int*)d_in[1];
    const int*   etype = (const int*)d_in[2];
    const float* w1    = (const float*)d_in[3];
    const float* b1    = (const float*)d_in[4];
    const float* w2    = (const float*)d_in[5];
    const float* b2    = (const float*)d_in[6];
    const float* rel   = (const float*)d_in[7];
    const float* lin1  = (const float*)d_in[8];
    const float* line1 = (const float*)d_in[9];
    const float* atts1 = (const float*)d_in[10];
    const float* attd1 = (const float*)d_in[11];
    const float* atte1 = (const float*)d_in[12];
    const float* bias1 = (const float*)d_in[13];
    const float* lin2  = (const float*)d_in[14];
    const float* line2 = (const float*)d_in[15];
    const float* atts2 = (const float*)d_in[16];
    const float* attd2 = (const float*)d_in[17];
    const float* atte2 = (const float*)d_in[18];
    const float* bias2 = (const float*)d_in[19];

    const int N = out_size / DH;          // 20000
    const int E = in_sizes[1] / 2;        // 320000
    const int F = in_sizes[3] / 256;      // 518
    const int* src = eidx;
    const int* dst = eidx + E;

    float *hidden, *h0, *h1, *hlin, *as_, *ad_, *relproj;
    int *cnt, *ctr, *rowptr, *csrc, *ctype;
    cudaGetSymbolAddress((void**)&hidden, g_hidden);
    cudaGetSymbolAddress((void**)&h0, g_h0);
    cudaGetSymbolAddress((void**)&h1, g_h1);
    cudaGetSymbolAddress((void**)&hlin, g_hlin);
    cudaGetSymbolAddress((void**)&as_, g_as);
    cudaGetSymbolAddress((void**)&ad_, g_ad);
    cudaGetSymbolAddress((void**)&cnt, g_cnt);
    cudaGetSymbolAddress((void**)&ctr, g_ctr);
    cudaGetSymbolAddress((void**)&rowptr, g_rowptr);
    cudaGetSymbolAddress((void**)&csrc, g_csrc);
    cudaGetSymbolAddress((void**)&ctype, g_ctype);
    cudaGetSymbolAddress((void**)&relproj, g_relproj);

    // CSR build (same for both layers)
    zero2_kernel<<<(N + 255) / 256, 256>>>(cnt, ctr, N);
    hist_kernel<<<(E + 255) / 256, 256>>>(dst, E, cnt);
    scan_kernel<<<1, 1024>>>(cnt, rowptr, N);
    scatter_kernel<<<(E + 255) / 256, 256>>>(src, dst, etype, E, rowptr, ctr, csrc, ctype);

    // collapsed edge-attention tables
    relproj_kernel<<<1, 128>>>(rel, line1, atte1, relproj);
    relproj_kernel<<<1, 128>>>(rel, line2, atte2, relproj + 26 * HEADS);

    const int MB = (N + 127) / 128;
    const int AGG_B = (N + 7) / 8;
    const int NH = N * HEADS;

    // node encoder
    {
        dim3 g(256 / 128, MB);
        mma_gemm<true, true, false><<<g, 256>>>(N, 256, F, x, w1, b1, hidden,
                                                nullptr, nullptr, nullptr, nullptr);
    }
    {
        dim3 g(1, MB);
        mma_gemm<false, true, false><<<g, 256>>>(N, DH, 256, hidden, w2, b2, h0,
                                                 nullptr, nullptr, nullptr, nullptr);
    }

    // GAT layer 1: hlin GEMM with fused attention dots
    zeroatt_kernel<<<(NH + 255) / 256, 256>>>(as_, ad_, NH);
    {
        dim3 g(HD / 128, MB);
        mma_gemm<false, false, true><<<g, 256>>>(N, HD, DH, h0, lin1, nullptr, hlin,
                                                 atts1, attd1, as_, ad_);
    }
    gat_agg_kernel<<<AGG_B, 256>>>(hlin, as_, ad_, rowptr, csrc, ctype,
                                   relproj, bias1, h1, N);

    // GAT layer 2
    zeroatt_kernel<<<(NH + 255) / 256, 256>>>(as_, ad_, NH);
    {
        dim3 g(HD / 128, MB);
        mma_gemm<false, false, true><<<g, 256>>>(N, HD, DH, h1, lin2, nullptr, hlin,
                                                 atts2, attd2, as_, ad_);
    }
    gat_agg_kernel<<<AGG_B, 256>>>(hlin, as_, ad_, rowptr, csrc, ctype,
                                   relproj + 26 * HEADS, bias2, (float*)d_out, N);
}

// round 6
// speedup vs baseline: 2.6132x; 1.0644x over previous
#include <cuda_runtime.h>
#include <cstdint>

// ---------------- problem-size bounds (fixed by the dataset) ----------------
#define NMAX 20000
#define EMAX 320000
#define DH   128     // node embedding dim
#define HEADS 4
#define HD   512     // HEADS * DH
#define CAP  128     // cached edges per node (overflow recomputed)

// ---------------- device scratch (no allocations allowed) -------------------
__device__ float g_hidden[NMAX * 256];   // encoder hidden
__device__ float g_h0[NMAX * DH];        // encoder out
__device__ float g_h1[NMAX * DH];        // layer1 out
__device__ float g_hlin[NMAX * HD];      // h @ lin  (per layer, reused)
__device__ float g_as[NMAX * HEADS];
__device__ float g_ad[NMAX * HEADS];
__device__ int   g_cnt[NMAX];
__device__ int   g_ctr[NMAX];
__device__ int   g_rowptr[NMAX + 1];
__device__ int2  g_cedge[EMAX];               // packed {src, type} per CSR slot
__device__ float g_relproj[2 * 26 * HEADS];   // [layer][26][4]

// ---------------- small utility kernels -------------------------------------
__global__ void zero2_kernel(int* a, int* b, int n) {
    int i = blockIdx.x * blockDim.x + threadIdx.x;
    if (i < n) { a[i] = 0; b[i] = 0; }
}

__global__ void hist_kernel(const int* __restrict__ dst, int E, int* __restrict__ cnt) {
    int i = blockIdx.x * blockDim.x + threadIdx.x;
    if (i < E) atomicAdd(&cnt[dst[i]], 1);
}

// single-block exclusive scan of cnt[0..n) -> rowptr[0..n]
__global__ void scan_kernel(const int* __restrict__ cnt, int* __restrict__ rowptr, int n) {
    __shared__ int part[1024];
    int tid = threadIdx.x;
    int chunk = (n + 1023) / 1024;
    int b = tid * chunk;
    int e = min(b + chunk, n);
    int s = 0;
    for (int i = b; i < e; i++) s += cnt[i];
    part[tid] = s;
    __syncthreads();
    for (int off = 1; off < 1024; off <<= 1) {
        int v = (tid >= off) ? part[tid - off] : 0;
        __syncthreads();
        part[tid] += v;
        __syncthreads();
    }
    int run = (tid == 0) ? 0 : part[tid - 1];
    for (int i = b; i < e; i++) { rowptr[i] = run; run += cnt[i]; }
    if (tid == 0) rowptr[n] = part[1023];
}

__global__ void scatter_kernel(const int* __restrict__ src, const int* __restrict__ dst,
                               const int* __restrict__ type, int E,
                               const int* __restrict__ rowptr, int* __restrict__ ctr,
                               int2* __restrict__ cedge) {
    int i = blockIdx.x * blockDim.x + threadIdx.x;
    if (i < E) {
        int d = dst[i];
        int p = rowptr[d] + atomicAdd(&ctr[d], 1);
        cedge[p] = make_int2(src[i], type[i]);
    }
}

// relproj[layer][r][h]; grid = 2 blocks (one per layer)
__global__ void relproj_kernel(const float* __restrict__ rel_emb,
                               const float* __restrict__ line1,
                               const float* __restrict__ atte1,
                               const float* __restrict__ line2,
                               const float* __restrict__ atte2,
                               float* __restrict__ relproj) {
    const float* line = blockIdx.x ? line2 : line1;
    const float* atte = blockIdx.x ? atte2 : atte1;
    float* rp = relproj + blockIdx.x * 26 * HEADS;
    __shared__ float we[32 * HEADS];
    int tid = threadIdx.x;   // 128 threads
    {
        int k = tid >> 2, h = tid & 3;
        float s = 0.f;
        const float* lp = line + k * HD + h * DH;
        const float* ap = atte + h * DH;
        for (int d = 0; d < DH; d++) s += lp[d] * ap[d];
        we[k * HEADS + h] = s;
    }
    __syncthreads();
    if (tid < 26 * HEADS) {
        int r = tid >> 2, h = tid & 3;
        float s = 0.f;
        for (int k = 0; k < 32; k++) s += rel_emb[r * 32 + k] * we[k * HEADS + h];
        rp[tid] = s;
    }
}

// ---------------- tf32 tensor-core GEMM (cp.async, depth-2 lookahead) --------
__device__ __forceinline__ uint32_t f2tf32(float f) {
    uint32_t u;
    asm("cvt.rna.tf32.f32 %0, %1;" : "=r"(u) : "f"(f));
    return u;
}

__device__ __forceinline__ void mma_tf32(float c[4], const uint32_t a[4], const uint32_t b[2]) {
    asm volatile(
        "mma.sync.aligned.m16n8k8.row.col.f32.tf32.tf32.f32 "
        "{%0,%1,%2,%3}, {%4,%5,%6,%7}, {%8,%9}, {%0,%1,%2,%3};"
        : "+f"(c[0]), "+f"(c[1]), "+f"(c[2]), "+f"(c[3])
        : "r"(a[0]), "r"(a[1]), "r"(a[2]), "r"(a[3]), "r"(b[0]), "r"(b[1]));
}

__device__ __forceinline__ void cp4(uint32_t smem_u32, const float* gptr, bool pred) {
    int sz = pred ? 4 : 0;
    asm volatile("cp.async.ca.shared.global [%0], [%1], 4, %2;"
                 :: "r"(smem_u32), "l"(gptr), "r"(sz));
}
__device__ __forceinline__ void cp_commit() {
    asm volatile("cp.async.commit_group;");
}
template <int N>
__device__ __forceinline__ void cp_wait() {
    asm volatile("cp.async.wait_group %0;" :: "n"(N));
}

// C = act(A[M,K] @ B[K,N] + bias). BM=128 BN=128 BK=16, 8 warps (2m x 4n),
// warp tile 64x32 = 4x4 m16n8k8 atoms. 2 smem stages, issued 2 tiles ahead.
// If ATT: BN==DH, blockIdx.x = head; per-row dots vs atts/attd reduced in smem
// and stored (full overwrite) to as_/ad_.
template <bool RELU, bool HAS_BIAS, bool ATT>
__global__ __launch_bounds__(256, 2) void mma_gemm(
        int M, int N, int K,
        const float* __restrict__ A, const float* __restrict__ B,
        const float* __restrict__ bias, float* __restrict__ C,
        const float* __restrict__ atts, const float* __restrict__ attd,
        float* __restrict__ as_, float* __restrict__ ad_) {
    constexpr int BM = 128, BN = 128, BK = 16;
    constexpr int AP = 20;    // A smem pitch: frag banks 20*qr+qc -> all 32 distinct
    constexpr int BP = 136;   // B smem pitch: frag banks 8*qc+qr -> all 32 distinct
    __shared__ float As[2][BM * AP];
    __shared__ float Bs[2][BK * BP];
    __shared__ float s_att[BM * 2];      // ATT reduction (1KB)

    const int tid  = threadIdx.x;
    const int lane = tid & 31;
    const int warp = tid >> 5;
    const int warpM = warp >> 2;
    const int warpN = warp & 3;
    const int bm = blockIdx.y * BM;
    const int bn = blockIdx.x * BN;
    const int mBase = warpM * 64;
    const int nBase = warpN * 32;
    const int qr = lane >> 2;
    const int qc = lane & 3;

    const uint32_t sA0 = (uint32_t)__cvta_generic_to_shared(&As[0][0]);
    const uint32_t sA1 = (uint32_t)__cvta_generic_to_shared(&As[1][0]);
    const uint32_t sB0 = (uint32_t)__cvta_generic_to_shared(&Bs[0][0]);
    const uint32_t sB1 = (uint32_t)__cvta_generic_to_shared(&Bs[1][0]);

    float acc[4][4][4] = {};

    auto issue = [&](int kt, int s) {
        const uint32_t aBase = s ? sA1 : sA0;
        const uint32_t bBase = s ? sB1 : sB0;
#pragma unroll
        for (int i = 0; i < 8; i++) {        // A: 128x16
            int idx = i * 256 + tid;
            int r = idx >> 4, c = idx & 15;
            int gr = bm + r, gc = kt + c;
            cp4(aBase + (uint32_t)(r * AP + c) * 4,
                A + (long)gr * K + gc, (gr < M) && (gc < K));
        }
#pragma unroll
        for (int i = 0; i < 8; i++) {        // B: 16x128
            int idx = i * 256 + tid;
            int r = idx >> 7, c = idx & 127;
            int gr = kt + r;
            cp4(bBase + (uint32_t)(r * BP + c) * 4,
                B + (long)gr * N + bn + c, gr < K);
        }
        cp_commit();
    };

    const int nkt = (K + BK - 1) / BK;
    issue(0, 0);
    if (nkt > 1) issue(BK, 1);

    int s = 0;
    for (int it = 0; it < nkt; it++, s ^= 1) {
        if (it + 1 < nkt) cp_wait<1>(); else cp_wait<0>();
        __syncthreads();

        const float* Acur = As[s];
        const float* Bcur = Bs[s];
#pragma unroll
        for (int ks = 0; ks < 2; ks++) {
            const int k0 = ks * 8 + qc;
            uint32_t af[4][4], bf[4][2];
#pragma unroll
            for (int am = 0; am < 4; am++) {
                int r0 = mBase + am * 16 + qr;
                af[am][0] = f2tf32(Acur[r0 * AP + k0]);
                af[am][1] = f2tf32(Acur[(r0 + 8) * AP + k0]);
                af[am][2] = f2tf32(Acur[r0 * AP + k0 + 4]);
                af[am][3] = f2tf32(Acur[(r0 + 8) * AP + k0 + 4]);
            }
#pragma unroll
            for (int bnn = 0; bnn < 4; bnn++) {
                int c0 = nBase + bnn * 8 + qr;
                bf[bnn][0] = f2tf32(Bcur[k0 * BP + c0]);
                bf[bnn][1] = f2tf32(Bcur[(k0 + 4) * BP + c0]);
            }
#pragma unroll
            for (int am = 0; am < 4; am++)
#pragma unroll
                for (int bnn = 0; bnn < 4; bnn++)
                    mma_tf32(acc[am][bnn], af[am], bf[bnn]);
        }
        __syncthreads();
        if (it + 2 < nkt) issue((it + 2) * BK, s);
    }

    // ---- epilogue: C store ----
#pragma unroll
    for (int am = 0; am < 4; am++) {
        int r0 = bm + mBase + am * 16 + qr;
#pragma unroll
        for (int bnn = 0; bnn < 4; bnn++) {
            int c0 = bn + nBase + bnn * 8 + 2 * qc;
            float b0 = 0.f, b1 = 0.f;
            if (HAS_BIAS) { b0 = bias[c0]; b1 = bias[c0 + 1]; }
#pragma unroll
            for (int half = 0; half < 2; half++) {
                int gr = r0 + half * 8;
                if (gr >= M) continue;
                float v0 = acc[am][bnn][half * 2 + 0] + b0;
                float v1 = acc[am][bnn][half * 2 + 1] + b1;
                if (RELU) { v0 = fmaxf(v0, 0.f); v1 = fmaxf(v1, 0.f); }
                *reinterpret_cast<float2*>(&C[(long)gr * N + c0]) = make_float2(v0, v1);
            }
        }
    }

    if (ATT) {
        const int hh = blockIdx.x;                   // head (BN==DH==128)
        float w0s[4], w1s[4], w0d[4], w1d[4];
#pragma unroll
        for (int bnn = 0; bnn < 4; bnn++) {
            int cl = nBase + bnn * 8 + 2 * qc;       // local col 0..127
            w0s[bnn] = atts[hh * DH + cl];  w1s[bnn] = atts[hh * DH + cl + 1];
            w0d[bnn] = attd[hh * DH + cl];  w1d[bnn] = attd[hh * DH + cl + 1];
        }
        float ps[4][2], pd[4][2];
#pragma unroll
        for (int am = 0; am < 4; am++)
#pragma unroll
            for (int half = 0; half < 2; half++) {
                float s_ = 0.f, d_ = 0.f;
#pragma unroll
                for (int bnn = 0; bnn < 4; bnn++) {
                    float v0 = acc[am][bnn][half * 2 + 0];
                    float v1 = acc[am][bnn][half * 2 + 1];
                    s_ += v0 * w0s[bnn] + v1 * w1s[bnn];
                    d_ += v0 * w0d[bnn] + v1 * w1d[bnn];
                }
                ps[am][half] = s_; pd[am][half] = d_;
            }
        // reduce over qc lanes (bits 0..1 of lane)
#pragma unroll
        for (int off = 1; off <= 2; off <<= 1)
#pragma unroll
            for (int am = 0; am < 4; am++)
#pragma unroll
                for (int half = 0; half < 2; half++) {
                    ps[am][half] += __shfl_xor_sync(~0u, ps[am][half], off);
                    pd[am][half] += __shfl_xor_sync(~0u, pd[am][half], off);
                }
        // reduce across warpN via smem, then one plain store per (row,comp)
        s_att[tid] = 0.f;
        if (tid < BM * 2 - 256) s_att[256 + tid] = 0.f;
        __syncthreads();
        if (qc == 0) {
#pragma unroll
            for (int am = 0; am < 4; am++)
#pragma unroll
                for (int half = 0; half < 2; half++) {
                    int lr = mBase + am * 16 + qr + half * 8;   // 0..127
                    atomicAdd(&s_att[lr * 2 + 0], ps[am][half]);
                    atomicAdd(&s_att[lr * 2 + 1], pd[am][half]);
                }
        }
        __syncthreads();
        {
            int lr = tid >> 1, comp = tid & 1;       // 256 threads cover 128x2
            int gr = bm + lr;
            if (gr < M) {
                float v = s_att[lr * 2 + comp];
                if (comp) ad_[gr * HEADS + hh] = v;
                else      as_[gr * HEADS + hh] = v;
            }
        }
    }
}

// ---------------- GAT aggregation: one WARP per destination node -------------
__device__ __forceinline__ float leaky02(float x) {
    return (x > 0.f) ? x : 0.2f * x;
}

__global__ __launch_bounds__(256) void gat_agg_kernel(
        const float* __restrict__ hlin,
        const float* __restrict__ a_s,
        const float* __restrict__ a_d,
        const int* __restrict__ rowptr,
        const int2* __restrict__ cedge,
        const float* __restrict__ relproj,
        const float* __restrict__ bias,
        float* __restrict__ out, int N) {
    const int w    = threadIdx.x >> 5;     // warp in block (8)
    const int lane = threadIdx.x & 31;
    const int n    = blockIdx.x * 8 + w;

    __shared__ __align__(16) float s_rp[32 * HEADS];   // relproj table (26 used)
    __shared__ __align__(16) float s_l[8][CAP][HEADS]; // logits -> alphas (16KB)
    __shared__ int s_src[8][CAP];                      // cached src ids (4KB)

    if (threadIdx.x < 26 * HEADS) s_rp[threadIdx.x] = relproj[threadIdx.x];
    __syncthreads();
    if (n >= N) return;

    const int beg = rowptr[n], end = rowptr[n + 1];
    const int deg = end - beg;

    const float4 ad4 = *reinterpret_cast<const float4*>(a_d + n * HEADS);

    // ---- phase A: logits for all incoming edges (lanes parallel) ----
    float m0 = -1e30f, m1 = -1e30f, m2 = -1e30f, m3 = -1e30f;
    float s0 = 0.f, s1 = 0.f, s2 = 0.f, s3 = 0.f;
    float r0 = 0.f, r1 = 0.f, r2 = 0.f, r3 = 0.f;       // sum of relproj (self-loop mean)
    for (int j = lane; j < deg; j += 32) {
        const int2 st = cedge[beg + j];
        const int sp = st.x;
        const int tp = st.y;
        const float4 as4 = *reinterpret_cast<const float4*>(a_s + sp * HEADS);
        const float4 rp4 = *reinterpret_cast<const float4*>(s_rp + tp * HEADS);
        float l0 = leaky02(as4.x + ad4.x + rp4.x);
        float l1 = leaky02(as4.y + ad4.y + rp4.y);
        float l2 = leaky02(as4.z + ad4.z + rp4.z);
        float l3 = leaky02(as4.w + ad4.w + rp4.w);
        r0 += rp4.x; r1 += rp4.y; r2 += rp4.z; r3 += rp4.w;
        if (j < CAP) {
            s_src[w][j] = sp;
            *reinterpret_cast<float4*>(s_l[w][j]) = make_float4(l0, l1, l2, l3);
        }
        if (l0 > m0) { s0 = s0 * __expf(m0 - l0) + 1.f; m0 = l0; } else s0 += __expf(l0 - m0);
        if (l1 > m1) { s1 = s1 * __expf(m1 - l1) + 1.f; m1 = l1; } else s1 += __expf(l1 - m1);
        if (l2 > m2) { s2 = s2 * __expf(m2 - l2) + 1.f; m2 = l2; } else s2 += __expf(l2 - m2);
        if (l3 > m3) { s3 = s3 * __expf(m3 - l3) + 1.f; m3 = l3; } else s3 += __expf(l3 - m3);
    }
#pragma unroll
    for (int off = 16; off > 0; off >>= 1) {
        float mo, so;
        mo = __shfl_xor_sync(~0u, m0, off); so = __shfl_xor_sync(~0u, s0, off);
        if (mo > m0) { s0 = s0 * __expf(m0 - mo) + so; m0 = mo; } else s0 += so * __expf(mo - m0);
        mo = __shfl_xor_sync(~0u, m1, off); so = __shfl_xor_sync(~0u, s1, off);
        if (mo > m1) { s1 = s1 * __expf(m1 - mo) + so; m1 = mo; } else s1 += so * __expf(mo - m1);
        mo = __shfl_xor_sync(~0u, m2, off); so = __shfl_xor_sync(~0u, s2, off);
        if (mo > m2) { s2 = s2 * __expf(m2 - mo) + so; m2 = mo; } else s2 += so * __expf(mo - m2);
        mo = __shfl_xor_sync(~0u, m3, off); so = __shfl_xor_sync(~0u, s3, off);
        if (mo > m3) { s3 = s3 * __expf(m3 - mo) + so; m3 = mo; } else s3 += so * __expf(mo - m3);
        r0 += __shfl_xor_sync(~0u, r0, off);
        r1 += __shfl_xor_sync(~0u, r1, off);
        r2 += __shfl_xor_sync(~0u, r2, off);
        r3 += __shfl_xor_sync(~0u, r3, off);
    }

    // self loop: a_e = mean of relproj over incoming edges
    const float4 asn = *reinterpret_cast<const float4*>(a_s + n * HEADS);
    const float dinv = 1.f / (float)max(deg, 1);
    float ls0 = leaky02(asn.x + ad4.x + r0 * dinv);
    float ls1 = leaky02(asn.y + ad4.y + r1 * dinv);
    float ls2 = leaky02(asn.z + ad4.z + r2 * dinv);
    float ls3 = leaky02(asn.w + ad4.w + r3 * dinv);
    if (ls0 > m0) { s0 = s0 * __expf(m0 - ls0) + 1.f; m0 = ls0; } else s0 += __expf(ls0 - m0);
    if (ls1 > m1) { s1 = s1 * __expf(m1 - ls1) + 1.f; m1 = ls1; } else s1 += __expf(ls1 - m1);
    if (ls2 > m2) { s2 = s2 * __expf(m2 - ls2) + 1.f; m2 = ls2; } else s2 += __expf(ls2 - m2);
    if (ls3 > m3) { s3 = s3 * __expf(m3 - ls3) + 1.f; m3 = ls3; } else s3 += __expf(ls3 - m3);
    const float i0 = 1.f / (s0 + 1e-16f), i1 = 1.f / (s1 + 1e-16f);
    const float i2 = 1.f / (s2 + 1e-16f), i3 = 1.f / (s3 + 1e-16f);
    const float la0 = __expf(ls0 - m0) * i0, la1 = __expf(ls1 - m1) * i1;
    const float la2 = __expf(ls2 - m2) * i2, la3 = __expf(ls3 - m3) * i3;

    __syncwarp();
    const int ncached = min(deg, CAP);
    for (int j = lane; j < ncached; j += 32) {
        float4 l4 = *reinterpret_cast<float4*>(s_l[w][j]);
        l4.x = __expf(l4.x - m0) * i0;
        l4.y = __expf(l4.y - m1) * i1;
        l4.z = __expf(l4.z - m2) * i2;
        l4.w = __expf(l4.w - m3) * i3;
        *reinterpret_cast<float4*>(s_l[w][j]) = l4;
    }
    __syncwarp();

    // ---- phase B: weighted accumulation, lane L -> dims [4L,4L+4) per head.
    const float4* hn = reinterpret_cast<const float4*>(hlin + (long)n * HD) + lane;
    float4 a0, a1, a2, a3;
    {
        float4 v;
        v = hn[0];  a0 = make_float4(la0 * v.x, la0 * v.y, la0 * v.z, la0 * v.w);
        v = hn[32]; a1 = make_float4(la1 * v.x, la1 * v.y, la1 * v.z, la1 * v.w);
        v = hn[64]; a2 = make_float4(la2 * v.x, la2 * v.y, la2 * v.z, la2 * v.w);
        v = hn[96]; a3 = make_float4(la3 * v.x, la3 * v.y, la3 * v.z, la3 * v.w);
    }
    // branchless main loop over cached edges
#pragma unroll 4
    for (int j = 0; j < ncached; j++) {
        const int sp = s_src[w][j];
        const float4 al = *reinterpret_cast<const float4*>(s_l[w][j]);
        const float4* hs = reinterpret_cast<const float4*>(hlin + (long)sp * HD) + lane;
        const float4 v0 = hs[0], v1 = hs[32], v2 = hs[64], v3 = hs[96];
        a0.x += al.x * v0.x; a0.y += al.x * v0.y; a0.z += al.x * v0.z; a0.w += al.x * v0.w;
        a1.x += al.y * v1.x; a1.y += al.y * v1.y; a1.z += al.y * v1.z; a1.w += al.y * v1.w;
        a2.x += al.z * v2.x; a2.y += al.z * v2.y; a2.z += al.z * v2.z; a2.w += al.z * v2.w;
        a3.x += al.w * v3.x; a3.y += al.w * v3.y; a3.z += al.w * v3.z; a3.w += al.w * v3.w;
    }
    // overflow tail (deg > CAP): recompute alphas
    for (int j = CAP; j < deg; j++) {
        const int2 st = cedge[beg + j];
        const int sp = st.x;
        const float4 as4 = *reinterpret_cast<const float4*>(a_s + sp * HEADS);
        const float4 rp4 = *reinterpret_cast<const float4*>(s_rp + st.y * HEADS);
        float4 al;
        al.x = __expf(leaky02(as4.x + ad4.x + rp4.x) - m0) * i0;
        al.y = __expf(leaky02(as4.y + ad4.y + rp4.y) - m1) * i1;
        al.z = __expf(leaky02(as4.z + ad4.z + rp4.z) - m2) * i2;
        al.w = __expf(leaky02(as4.w + ad4.w + rp4.w) - m3) * i3;
        const float4* hs = reinterpret_cast<const float4*>(hlin + (long)sp * HD) + lane;
        const float4 v0 = hs[0], v1 = hs[32], v2 = hs[64], v3 = hs[96];
        a0.x += al.x * v0.x; a0.y += al.x * v0.y; a0.z += al.x * v0.z; a0.w += al.x * v0.w;
        a1.x += al.y * v1.x; a1.y += al.y * v1.y; a1.z += al.y * v1.z; a1.w += al.y * v1.w;
        a2.x += al.z * v2.x; a2.y += al.z * v2.y; a2.z += al.z * v2.z; a2.w += al.z * v2.w;
        a3.x += al.w * v3.x; a3.y += al.w * v3.y; a3.z += al.w * v3.z; a3.w += al.w * v3.w;
    }

    const float4 b4 = *reinterpret_cast<const float4*>(bias + 4 * lane);
    float4 o;
    o.x = fmaxf(0.25f * (a0.x + a1.x + a2.x + a3.x) + b4.x, 0.f);
    o.y = fmaxf(0.25f * (a0.y + a1.y + a2.y + a3.y) + b4.y, 0.f);
    o.z = fmaxf(0.25f * (a0.z + a1.z + a2.z + a3.z) + b4.z, 0.f);
    o.w = fmaxf(0.25f * (a0.w + a1.w + a2.w + a3.w) + b4.w, 0.f);
    *reinterpret_cast<float4*>(out + (long)n * DH + 4 * lane) = o;
}

// ---------------- launch ------------------------------------------------------
extern "C" void kernel_launch(void* const* d_in, const int* in_sizes, int n_in,
                              void* d_out, int out_size) {
    const float* x     = (const float*)d_in[0];
    const int*   eidx  = (const int*)d_in[1];
    const int*   etype = (const int*)d_in[2];
    const float* w1    = (const float*)d_in[3];
    const float* b1    = (const float*)d_in[4];
    const float* w2    = (const float*)d_in[5];
    const float* b2    = (const float*)d_in[6];
    const float* rel   = (const float*)d_in[7];
    const float* lin1  = (const float*)d_in[8];
    const float* line1 = (const float*)d_in[9];
    const float* atts1 = (const float*)d_in[10];
    const float* attd1 = (const float*)d_in[11];
    const float* atte1 = (const float*)d_in[12];
    const float* bias1 = (const float*)d_in[13];
    const float* lin2  = (const float*)d_in[14];
    const float* line2 = (const float*)d_in[15];
    const float* atts2 = (const float*)d_in[16];
    const float* attd2 = (const float*)d_in[17];
    const float* atte2 = (const float*)d_in[18];
    const float* bias2 = (const float*)d_in[19];

    const int N = out_size / DH;          // 20000
    const int E = in_sizes[1] / 2;        // 320000
    const int F = in_sizes[3] / 256;      // 518
    const int* src = eidx;
    const int* dst = eidx + E;

    float *hidden, *h0, *h1, *hlin, *as_, *ad_, *relproj;
    int *cnt, *ctr, *rowptr;
    int2* cedge;
    cudaGetSymbolAddress((void**)&hidden, g_hidden);
    cudaGetSymbolAddress((void**)&h0, g_h0);
    cudaGetSymbolAddress((void**)&h1, g_h1);
    cudaGetSymbolAddress((void**)&hlin, g_hlin);
    cudaGetSymbolAddress((void**)&as_, g_as);
    cudaGetSymbolAddress((void**)&ad_, g_ad);
    cudaGetSymbolAddress((void**)&cnt, g_cnt);
    cudaGetSymbolAddress((void**)&ctr, g_ctr);
    cudaGetSymbolAddress((void**)&rowptr, g_rowptr);
    cudaGetSymbolAddress((void**)&cedge, g_cedge);
    cudaGetSymbolAddress((void**)&relproj, g_relproj);

    // CSR build (same for both layers)
    zero2_kernel<<<(N + 255) / 256, 256>>>(cnt, ctr, N);
    hist_kernel<<<(E + 255) / 256, 256>>>(dst, E, cnt);
    scan_kernel<<<1, 1024>>>(cnt, rowptr, N);
    scatter_kernel<<<(E + 255) / 256, 256>>>(src, dst, etype, E, rowptr, ctr, cedge);

    // collapsed edge-attention tables (both layers, one launch)
    relproj_kernel<<<2, 128>>>(rel, line1, atte1, line2, atte2, relproj);

    const int MB = (N + 127) / 128;
    const int AGG_B = (N + 7) / 8;

    // node encoder
    {
        dim3 g(256 / 128, MB);
        mma_gemm<true, true, false><<<g, 256>>>(N, 256, F, x, w1, b1, hidden,
                                                nullptr, nullptr, nullptr, nullptr);
    }
    {
        dim3 g(1, MB);
        mma_gemm<false, true, false><<<g, 256>>>(N, DH, 256, hidden, w2, b2, h0,
                                                 nullptr, nullptr, nullptr, nullptr);
    }

    // GAT layer 1: hlin GEMM with fused attention dots (full overwrite of as_/ad_)
    {
        dim3 g(HD / 128, MB);
        mma_gemm<false, false, true><<<g, 256>>>(N, HD, DH, h0, lin1, nullptr, hlin,
                                                 atts1, attd1, as_, ad_);
    }
    gat_agg_kernel<<<AGG_B, 256>>>(hlin, as_, ad_, rowptr, cedge,
                                   relproj, bias1, h1, N);

    // GAT layer 2
    {
        dim3 g(HD / 128, MB);
        mma_gemm<false, false, true><<<g, 256>>>(N, HD, DH, h1, lin2, nullptr, hlin,
                                                 atts2, attd2, as_, ad_);
    }
    gat_agg_kernel<<<AGG_B, 256>>>(hlin, as_, ad_, rowptr, cedge,
                                   relproj + 26 * HEADS, bias2, (float*)d_out, N);
}

// round 7
// speedup vs baseline: 2.7524x; 1.0532x over previous
#include <cuda_runtime.h>
#include <cuda_fp16.h>
#include <cstdint>

// ---------------- problem-size bounds (fixed by the dataset) ----------------
#define NMAX 20000
#define EMAX 320000
#define DH   128     // node embedding dim
#define HEADS 4
#define HD   512     // HEADS * DH
#define CAP  128     // cached edges per node (overflow recomputed)

// ---------------- device scratch (no allocations allowed) -------------------
__device__ float  g_hidden[NMAX * 256];   // encoder hidden
__device__ float  g_h0[NMAX * DH];        // encoder out
__device__ float  g_h1[NMAX * DH];        // layer1 out
__device__ __half g_hlinh[NMAX * HD];     // h @ lin in fp16, layout [n][L][head][4]
__device__ float  g_as[NMAX * HEADS];
__device__ float  g_ad[NMAX * HEADS];
__device__ int    g_cnt[NMAX];
__device__ int    g_ctr[NMAX];
__device__ int    g_rowptr[NMAX + 1];
__device__ int2   g_cedge[EMAX];               // packed {src, type} per CSR slot
__device__ float  g_relproj[2 * 26 * HEADS];   // [layer][26][4]

// ---------------- small utility kernels -------------------------------------
__global__ void zero2_kernel(int* a, int* b, int n) {
    int i = blockIdx.x * blockDim.x + threadIdx.x;
    if (i < n) { a[i] = 0; b[i] = 0; }
}

__global__ void hist_kernel(const int* __restrict__ dst, int E, int* __restrict__ cnt) {
    int i = blockIdx.x * blockDim.x + threadIdx.x;
    if (i < E) atomicAdd(&cnt[dst[i]], 1);
}

// single-block exclusive scan of cnt[0..n) -> rowptr[0..n]
__global__ void scan_kernel(const int* __restrict__ cnt, int* __restrict__ rowptr, int n) {
    __shared__ int part[1024];
    int tid = threadIdx.x;
    int chunk = (n + 1023) / 1024;
    int b = tid * chunk;
    int e = min(b + chunk, n);
    int s = 0;
    for (int i = b; i < e; i++) s += cnt[i];
    part[tid] = s;
    __syncthreads();
    for (int off = 1; off < 1024; off <<= 1) {
        int v = (tid >= off) ? part[tid - off] : 0;
        __syncthreads();
        part[tid] += v;
        __syncthreads();
    }
    int run = (tid == 0) ? 0 : part[tid - 1];
    for (int i = b; i < e; i++) { rowptr[i] = run; run += cnt[i]; }
    if (tid == 0) rowptr[n] = part[1023];
}

__global__ void scatter_kernel(const int* __restrict__ src, const int* __restrict__ dst,
                               const int* __restrict__ type, int E,
                               const int* __restrict__ rowptr, int* __restrict__ ctr,
                               int2* __restrict__ cedge) {
    int i = blockIdx.x * blockDim.x + threadIdx.x;
    if (i < E) {
        int d = dst[i];
        int p = rowptr[d] + atomicAdd(&ctr[d], 1);
        cedge[p] = make_int2(src[i], type[i]);
    }
}

// relproj[layer][r][h]; grid = 2 blocks (one per layer)
__global__ void relproj_kernel(const float* __restrict__ rel_emb,
                               const float* __restrict__ line1,
                               const float* __restrict__ atte1,
                               const float* __restrict__ line2,
                               const float* __restrict__ atte2,
                               float* __restrict__ relproj) {
    const float* line = blockIdx.x ? line2 : line1;
    const float* atte = blockIdx.x ? atte2 : atte1;
    float* rp = relproj + blockIdx.x * 26 * HEADS;
    __shared__ float we[32 * HEADS];
    int tid = threadIdx.x;   // 128 threads
    {
        int k = tid >> 2, h = tid & 3;
        float s = 0.f;
        const float* lp = line + k * HD + h * DH;
        const float* ap = atte + h * DH;
        for (int d = 0; d < DH; d++) s += lp[d] * ap[d];
        we[k * HEADS + h] = s;
    }
    __syncthreads();
    if (tid < 26 * HEADS) {
        int r = tid >> 2, h = tid & 3;
        float s = 0.f;
        for (int k = 0; k < 32; k++) s += rel_emb[r * 32 + k] * we[k * HEADS + h];
        rp[tid] = s;
    }
}

// ---------------- tf32 tensor-core GEMM (cp.async, depth-2 lookahead) --------
__device__ __forceinline__ uint32_t f2tf32(float f) {
    uint32_t u;
    asm("cvt.rna.tf32.f32 %0, %1;" : "=r"(u) : "f"(f));
    return u;
}

__device__ __forceinline__ void mma_tf32(float c[4], const uint32_t a[4], const uint32_t b[2]) {
    asm volatile(
        "mma.sync.aligned.m16n8k8.row.col.f32.tf32.tf32.f32 "
        "{%0,%1,%2,%3}, {%4,%5,%6,%7}, {%8,%9}, {%0,%1,%2,%3};"
        : "+f"(c[0]), "+f"(c[1]), "+f"(c[2]), "+f"(c[3])
        : "r"(a[0]), "r"(a[1]), "r"(a[2]), "r"(a[3]), "r"(b[0]), "r"(b[1]));
}

__device__ __forceinline__ void cp4(uint32_t smem_u32, const float* gptr, bool pred) {
    int sz = pred ? 4 : 0;
    asm volatile("cp.async.ca.shared.global [%0], [%1], 4, %2;"
                 :: "r"(smem_u32), "l"(gptr), "r"(sz));
}
__device__ __forceinline__ void cp_commit() {
    asm volatile("cp.async.commit_group;");
}
template <int N>
__device__ __forceinline__ void cp_wait() {
    asm volatile("cp.async.wait_group %0;" :: "n"(N));
}

// C = act(A[M,K] @ B[K,N] + bias). BM=128 BN=128 BK=16, 8 warps (2m x 4n).
// If ATT: BN==DH, blockIdx.x = head hh. Instead of storing fp32 C, stores
// fp16 into Ch with layout [row][L=cl/4][head][cl%4] (HD halves per row),
// and computes per-row dots vs atts/attd -> as_/ad_ (full overwrite).
template <bool RELU, bool HAS_BIAS, bool ATT>
__global__ __launch_bounds__(256, 2) void mma_gemm(
        int M, int N, int K,
        const float* __restrict__ A, const float* __restrict__ B,
        const float* __restrict__ bias, float* __restrict__ C,
        __half* __restrict__ Ch,
        const float* __restrict__ atts, const float* __restrict__ attd,
        float* __restrict__ as_, float* __restrict__ ad_) {
    constexpr int BM = 128, BN = 128, BK = 16;
    constexpr int AP = 20;    // A smem pitch: frag banks conflict-free
    constexpr int BP = 136;   // B smem pitch: frag banks conflict-free
    __shared__ float As[2][BM * AP];
    __shared__ float Bs[2][BK * BP];
    __shared__ float s_att[BM * 2];      // ATT reduction (1KB)

    const int tid  = threadIdx.x;
    const int lane = tid & 31;
    const int warp = tid >> 5;
    const int warpM = warp >> 2;
    const int warpN = warp & 3;
    const int bm = blockIdx.y * BM;
    const int bn = blockIdx.x * BN;
    const int mBase = warpM * 64;
    const int nBase = warpN * 32;
    const int qr = lane >> 2;
    const int qc = lane & 3;

    const uint32_t sA0 = (uint32_t)__cvta_generic_to_shared(&As[0][0]);
    const uint32_t sA1 = (uint32_t)__cvta_generic_to_shared(&As[1][0]);
    const uint32_t sB0 = (uint32_t)__cvta_generic_to_shared(&Bs[0][0]);
    const uint32_t sB1 = (uint32_t)__cvta_generic_to_shared(&Bs[1][0]);

    float acc[4][4][4] = {};

    auto issue = [&](int kt, int s) {
        const uint32_t aBase = s ? sA1 : sA0;
        const uint32_t bBase = s ? sB1 : sB0;
#pragma unroll
        for (int i = 0; i < 8; i++) {        // A: 128x16
            int idx = i * 256 + tid;
            int r = idx >> 4, c = idx & 15;
            int gr = bm + r, gc = kt + c;
            cp4(aBase + (uint32_t)(r * AP + c) * 4,
                A + (long)gr * K + gc, (gr < M) && (gc < K));
        }
#pragma unroll
        for (int i = 0; i < 8; i++) {        // B: 16x128
            int idx = i * 256 + tid;
            int r = idx >> 7, c = idx & 127;
            int gr = kt + r;
            cp4(bBase + (uint32_t)(r * BP + c) * 4,
                B + (long)gr * N + bn + c, gr < K);
        }
        cp_commit();
    };

    const int nkt = (K + BK - 1) / BK;
    issue(0, 0);
    if (nkt > 1) issue(BK, 1);

    int s = 0;
    for (int it = 0; it < nkt; it++, s ^= 1) {
        if (it + 1 < nkt) cp_wait<1>(); else cp_wait<0>();
        __syncthreads();

        const float* Acur = As[s];
        const float* Bcur = Bs[s];
#pragma unroll
        for (int ks = 0; ks < 2; ks++) {
            const int k0 = ks * 8 + qc;
            uint32_t af[4][4], bf[4][2];
#pragma unroll
            for (int am = 0; am < 4; am++) {
                int r0 = mBase + am * 16 + qr;
                af[am][0] = f2tf32(Acur[r0 * AP + k0]);
                af[am][1] = f2tf32(Acur[(r0 + 8) * AP + k0]);
                af[am][2] = f2tf32(Acur[r0 * AP + k0 + 4]);
                af[am][3] = f2tf32(Acur[(r0 + 8) * AP + k0 + 4]);
            }
#pragma unroll
            for (int bnn = 0; bnn < 4; bnn++) {
                int c0 = nBase + bnn * 8 + qr;
                bf[bnn][0] = f2tf32(Bcur[k0 * BP + c0]);
                bf[bnn][1] = f2tf32(Bcur[(k0 + 4) * BP + c0]);
            }
#pragma unroll
            for (int am = 0; am < 4; am++)
#pragma unroll
                for (int bnn = 0; bnn < 4; bnn++)
                    mma_tf32(acc[am][bnn], af[am], bf[bnn]);
        }
        __syncthreads();
        if (it + 2 < nkt) issue((it + 2) * BK, s);
    }

    // ---- epilogue ----
    if (!ATT) {
#pragma unroll
        for (int am = 0; am < 4; am++) {
            int r0 = bm + mBase + am * 16 + qr;
#pragma unroll
            for (int bnn = 0; bnn < 4; bnn++) {
                int c0 = bn + nBase + bnn * 8 + 2 * qc;
                float b0 = 0.f, b1 = 0.f;
                if (HAS_BIAS) { b0 = bias[c0]; b1 = bias[c0 + 1]; }
#pragma unroll
                for (int half = 0; half < 2; half++) {
                    int gr = r0 + half * 8;
                    if (gr >= M) continue;
                    float v0 = acc[am][bnn][half * 2 + 0] + b0;
                    float v1 = acc[am][bnn][half * 2 + 1] + b1;
                    if (RELU) { v0 = fmaxf(v0, 0.f); v1 = fmaxf(v1, 0.f); }
                    *reinterpret_cast<float2*>(&C[(long)gr * N + c0]) = make_float2(v0, v1);
                }
            }
        }
    } else {
        const int hh = blockIdx.x;                   // head (BN==DH==128)
        // fp16 store in agg layout: halves index = row*HD + L*16 + hh*4 + d
#pragma unroll
        for (int am = 0; am < 4; am++) {
            int r0 = bm + mBase + am * 16 + qr;
#pragma unroll
            for (int bnn = 0; bnn < 4; bnn++) {
                int cl = nBase + bnn * 8 + 2 * qc;   // head-local col (even)
                int L = cl >> 2, d = cl & 3;         // d in {0,2}
#pragma unroll
                for (int half = 0; half < 2; half++) {
                    int gr = r0 + half * 8;
                    if (gr >= M) continue;
                    float v0 = acc[am][bnn][half * 2 + 0];
                    float v1 = acc[am][bnn][half * 2 + 1];
                    __half2 hv = __floats2half2_rn(v0, v1);
                    *reinterpret_cast<__half2*>(
                        Ch + (long)gr * HD + L * 16 + hh * 4 + d) = hv;
                }
            }
        }
        // fused attention dots
        float w0s[4], w1s[4], w0d[4], w1d[4];
#pragma unroll
        for (int bnn = 0; bnn < 4; bnn++) {
            int cl = nBase + bnn * 8 + 2 * qc;
            w0s[bnn] = atts[hh * DH + cl];  w1s[bnn] = atts[hh * DH + cl + 1];
            w0d[bnn] = attd[hh * DH + cl];  w1d[bnn] = attd[hh * DH + cl + 1];
        }
        float ps[4][2], pd[4][2];
#pragma unroll
        for (int am = 0; am < 4; am++)
#pragma unroll
            for (int half = 0; half < 2; half++) {
                float s_ = 0.f, d_ = 0.f;
#pragma unroll
                for (int bnn = 0; bnn < 4; bnn++) {
                    float v0 = acc[am][bnn][half * 2 + 0];
                    float v1 = acc[am][bnn][half * 2 + 1];
                    s_ += v0 * w0s[bnn] + v1 * w1s[bnn];
                    d_ += v0 * w0d[bnn] + v1 * w1d[bnn];
                }
                ps[am][half] = s_; pd[am][half] = d_;
            }
#pragma unroll
        for (int off = 1; off <= 2; off <<= 1)
#pragma unroll
            for (int am = 0; am < 4; am++)
#pragma unroll
                for (int half = 0; half < 2; half++) {
                    ps[am][half] += __shfl_xor_sync(~0u, ps[am][half], off);
                    pd[am][half] += __shfl_xor_sync(~0u, pd[am][half], off);
                }
        s_att[tid] = 0.f;
        if (tid < BM * 2 - 256) s_att[256 + tid] = 0.f;
        __syncthreads();
        if (qc == 0) {
#pragma unroll
            for (int am = 0; am < 4; am++)
#pragma unroll
                for (int half = 0; half < 2; half++) {
                    int lr = mBase + am * 16 + qr + half * 8;   // 0..127
                    atomicAdd(&s_att[lr * 2 + 0], ps[am][half]);
                    atomicAdd(&s_att[lr * 2 + 1], pd[am][half]);
                }
        }
        __syncthreads();
        {
            int lr = tid >> 1, comp = tid & 1;
            int gr = bm + lr;
            if (gr < M) {
                float v = s_att[lr * 2 + comp];
                if (comp) ad_[gr * HEADS + hh] = v;
                else      as_[gr * HEADS + hh] = v;
            }
        }
    }
}

// ---------------- GAT aggregation: one WARP per destination node -------------
// hlinh layout: halves [n][L=0..31][head=0..3][d=0..3]; lane L reads its 32B
// (2 x LDG.128) per gathered node.
__device__ __forceinline__ float leaky02(float x) {
    return (x > 0.f) ? x : 0.2f * x;
}

__device__ __forceinline__ float4 unpack_head(uint32_t lo, uint32_t hi) {
    float2 a = __half22float2(*reinterpret_cast<const __half2*>(&lo));
    float2 b = __half22float2(*reinterpret_cast<const __half2*>(&hi));
    return make_float4(a.x, a.y, b.x, b.y);
}

__global__ __launch_bounds__(256) void gat_agg_kernel(
        const __half* __restrict__ hlinh,
        const float* __restrict__ a_s,
        const float* __restrict__ a_d,
        const int* __restrict__ rowptr,
        const int2* __restrict__ cedge,
        const float* __restrict__ relproj,
        const float* __restrict__ bias,
        float* __restrict__ out, int N) {
    const int w    = threadIdx.x >> 5;     // warp in block (8)
    const int lane = threadIdx.x & 31;
    const int n    = blockIdx.x * 8 + w;

    __shared__ __align__(16) float s_rp[32 * HEADS];   // relproj table (26 used)
    __shared__ __align__(16) float s_l[8][CAP][HEADS]; // logits -> alphas (16KB)
    __shared__ int s_src[8][CAP];                      // cached src ids (4KB)

    if (threadIdx.x < 26 * HEADS) s_rp[threadIdx.x] = relproj[threadIdx.x];
    __syncthreads();
    if (n >= N) return;

    const int beg = rowptr[n], end = rowptr[n + 1];
    const int deg = end - beg;

    const float4 ad4 = *reinterpret_cast<const float4*>(a_d + n * HEADS);

    // ---- phase A: logits for all incoming edges (lanes parallel) ----
    float m0 = -1e30f, m1 = -1e30f, m2 = -1e30f, m3 = -1e30f;
    float s0 = 0.f, s1 = 0.f, s2 = 0.f, s3 = 0.f;
    float r0 = 0.f, r1 = 0.f, r2 = 0.f, r3 = 0.f;
    for (int j = lane; j < deg; j += 32) {
        const int2 st = cedge[beg + j];
        const int sp = st.x;
        const int tp = st.y;
        const float4 as4 = *reinterpret_cast<const float4*>(a_s + sp * HEADS);
        const float4 rp4 = *reinterpret_cast<const float4*>(s_rp + tp * HEADS);
        float l0 = leaky02(as4.x + ad4.x + rp4.x);
        float l1 = leaky02(as4.y + ad4.y + rp4.y);
        float l2 = leaky02(as4.z + ad4.z + rp4.z);
        float l3 = leaky02(as4.w + ad4.w + rp4.w);
        r0 += rp4.x; r1 += rp4.y; r2 += rp4.z; r3 += rp4.w;
        if (j < CAP) {
            s_src[w][j] = sp;
            *reinterpret_cast<float4*>(s_l[w][j]) = make_float4(l0, l1, l2, l3);
        }
        if (l0 > m0) { s0 = s0 * __expf(m0 - l0) + 1.f; m0 = l0; } else s0 += __expf(l0 - m0);
        if (l1 > m1) { s1 = s1 * __expf(m1 - l1) + 1.f; m1 = l1; } else s1 += __expf(l1 - m1);
        if (l2 > m2) { s2 = s2 * __expf(m2 - l2) + 1.f; m2 = l2; } else s2 += __expf(l2 - m2);
        if (l3 > m3) { s3 = s3 * __expf(m3 - l3) + 1.f; m3 = l3; } else s3 += __expf(l3 - m3);
    }
#pragma unroll
    for (int off = 16; off > 0; off >>= 1) {
        float mo, so;
        mo = __shfl_xor_sync(~0u, m0, off); so = __shfl_xor_sync(~0u, s0, off);
        if (mo > m0) { s0 = s0 * __expf(m0 - mo) + so; m0 = mo; } else s0 += so * __expf(mo - m0);
        mo = __shfl_xor_sync(~0u, m1, off); so = __shfl_xor_sync(~0u, s1, off);
        if (mo > m1) { s1 = s1 * __expf(m1 - mo) + so; m1 = mo; } else s1 += so * __expf(mo - m1);
        mo = __shfl_xor_sync(~0u, m2, off); so = __shfl_xor_sync(~0u, s2, off);
        if (mo > m2) { s2 = s2 * __expf(m2 - mo) + so; m2 = mo; } else s2 += so * __expf(mo - m2);
        mo = __shfl_xor_sync(~0u, m3, off); so = __shfl_xor_sync(~0u, s3, off);
        if (mo > m3) { s3 = s3 * __expf(m3 - mo) + so; m3 = mo; } else s3 += so * __expf(mo - m3);
        r0 += __shfl_xor_sync(~0u, r0, off);
        r1 += __shfl_xor_sync(~0u, r1, off);
        r2 += __shfl_xor_sync(~0u, r2, off);
        r3 += __shfl_xor_sync(~0u, r3, off);
    }

    // self loop: a_e = mean of relproj over incoming edges
    const float4 asn = *reinterpret_cast<const float4*>(a_s + n * HEADS);
    const float dinv = 1.f / (float)max(deg, 1);
    float ls0 = leaky02(asn.x + ad4.x + r0 * dinv);
    float ls1 = leaky02(asn.y + ad4.y + r1 * dinv);
    float ls2 = leaky02(asn.z + ad4.z + r2 * dinv);
    float ls3 = leaky02(asn.w + ad4.w + r3 * dinv);
    if (ls0 > m0) { s0 = s0 * __expf(m0 - ls0) + 1.f; m0 = ls0; } else s0 += __expf(ls0 - m0);
    if (ls1 > m1) { s1 = s1 * __expf(m1 - ls1) + 1.f; m1 = ls1; } else s1 += __expf(ls1 - m1);
    if (ls2 > m2) { s2 = s2 * __expf(m2 - ls2) + 1.f; m2 = ls2; } else s2 += __expf(ls2 - m2);
    if (ls3 > m3) { s3 = s3 * __expf(m3 - ls3) + 1.f; m3 = ls3; } else s3 += __expf(ls3 - m3);
    const float i0 = 1.f / (s0 + 1e-16f), i1 = 1.f / (s1 + 1e-16f);
    const float i2 = 1.f / (s2 + 1e-16f), i3 = 1.f / (s3 + 1e-16f);
    const float la0 = __expf(ls0 - m0) * i0, la1 = __expf(ls1 - m1) * i1;
    const float la2 = __expf(ls2 - m2) * i2, la3 = __expf(ls3 - m3) * i3;

    __syncwarp();
    const int ncached = min(deg, CAP);
    for (int j = lane; j < ncached; j += 32) {
        float4 l4 = *reinterpret_cast<float4*>(s_l[w][j]);
        l4.x = __expf(l4.x - m0) * i0;
        l4.y = __expf(l4.y - m1) * i1;
        l4.z = __expf(l4.z - m2) * i2;
        l4.w = __expf(l4.w - m3) * i3;
        *reinterpret_cast<float4*>(s_l[w][j]) = l4;
    }
    __syncwarp();

    // ---- phase B: lane L owns dims [4L,4L+4) per head; 2 x LDG.128 per edge.
    float4 a0, a1, a2, a3;
    {
        const uint4* hp = reinterpret_cast<const uint4*>(hlinh + (long)n * HD) + lane * 2;
        const uint4 p0 = hp[0], p1 = hp[1];
        float4 v0 = unpack_head(p0.x, p0.y);
        float4 v1 = unpack_head(p0.z, p0.w);
        float4 v2 = unpack_head(p1.x, p1.y);
        float4 v3 = unpack_head(p1.z, p1.w);
        a0 = make_float4(la0 * v0.x, la0 * v0.y, la0 * v0.z, la0 * v0.w);
        a1 = make_float4(la1 * v1.x, la1 * v1.y, la1 * v1.z, la1 * v1.w);
        a2 = make_float4(la2 * v2.x, la2 * v2.y, la2 * v2.z, la2 * v2.w);
        a3 = make_float4(la3 * v3.x, la3 * v3.y, la3 * v3.z, la3 * v3.w);
    }
#pragma unroll 4
    for (int j = 0; j < ncached; j++) {
        const int sp = s_src[w][j];
        const float4 al = *reinterpret_cast<const float4*>(s_l[w][j]);
        const uint4* hp = reinterpret_cast<const uint4*>(hlinh + (long)sp * HD) + lane * 2;
        const uint4 p0 = hp[0], p1 = hp[1];
        const float4 v0 = unpack_head(p0.x, p0.y);
        const float4 v1 = unpack_head(p0.z, p0.w);
        const float4 v2 = unpack_head(p1.x, p1.y);
        const float4 v3 = unpack_head(p1.z, p1.w);
        a0.x += al.x * v0.x; a0.y += al.x * v0.y; a0.z += al.x * v0.z; a0.w += al.x * v0.w;
        a1.x += al.y * v1.x; a1.y += al.y * v1.y; a1.z += al.y * v1.z; a1.w += al.y * v1.w;
        a2.x += al.z * v2.x; a2.y += al.z * v2.y; a2.z += al.z * v2.z; a2.w += al.z * v2.w;
        a3.x += al.w * v3.x; a3.y += al.w * v3.y; a3.z += al.w * v3.z; a3.w += al.w * v3.w;
    }
    // overflow tail (deg > CAP): recompute alphas
    for (int j = CAP; j < deg; j++) {
        const int2 st = cedge[beg + j];
        const int sp = st.x;
        const float4 as4 = *reinterpret_cast<const float4*>(a_s + sp * HEADS);
        const float4 rp4 = *reinterpret_cast<const float4*>(s_rp + st.y * HEADS);
        float4 al;
        al.x = __expf(leaky02(as4.x + ad4.x + rp4.x) - m0) * i0;
        al.y = __expf(leaky02(as4.y + ad4.y + rp4.y) - m1) * i1;
        al.z = __expf(leaky02(as4.z + ad4.z + rp4.z) - m2) * i2;
        al.w = __expf(leaky02(as4.w + ad4.w + rp4.w) - m3) * i3;
        const uint4* hp = reinterpret_cast<const uint4*>(hlinh + (long)sp * HD) + lane * 2;
        const uint4 p0 = hp[0], p1 = hp[1];
        const float4 v0 = unpack_head(p0.x, p0.y);
        const float4 v1 = unpack_head(p0.z, p0.w);
        const float4 v2 = unpack_head(p1.x, p1.y);
        const float4 v3 = unpack_head(p1.z, p1.w);
        a0.x += al.x * v0.x; a0.y += al.x * v0.y; a0.z += al.x * v0.z; a0.w += al.x * v0.w;
        a1.x += al.y * v1.x; a1.y += al.y * v1.y; a1.z += al.y * v1.z; a1.w += al.y * v1.w;
        a2.x += al.z * v2.x; a2.y += al.z * v2.y; a2.z += al.z * v2.z; a2.w += al.z * v2.w;
        a3.x += al.w * v3.x; a3.y += al.w * v3.y; a3.z += al.w * v3.z; a3.w += al.w * v3.w;
    }

    const float4 b4 = *reinterpret_cast<const float4*>(bias + 4 * lane);
    float4 o;
    o.x = fmaxf(0.25f * (a0.x + a1.x + a2.x + a3.x) + b4.x, 0.f);
    o.y = fmaxf(0.25f * (a0.y + a1.y + a2.y + a3.y) + b4.y, 0.f);
    o.z = fmaxf(0.25f * (a0.z + a1.z + a2.z + a3.z) + b4.z, 0.f);
    o.w = fmaxf(0.25f * (a0.w + a1.w + a2.w + a3.w) + b4.w, 0.f);
    *reinterpret_cast<float4*>(out + (long)n * DH + 4 * lane) = o;
}

// ---------------- launch ------------------------------------------------------
extern "C" void kernel_launch(void* const* d_in, const int* in_sizes, int n_in,
                              void* d_out, int out_size) {
    const float* x     = (const float*)d_in[0];
    const int*   eidx  = (const int*)d_in[1];
    const int*   etype = (const int*)d_in[2];
    const float* w1    = (const float*)d_in[3];
    const float* b1    = (const float*)d_in[4];
    const float* w2    = (const float*)d_in[5];
    const float* b2    = (const float*)d_in[6];
    const float* rel   = (const float*)d_in[7];
    const float* lin1  = (const float*)d_in[8];
    const float* line1 = (const float*)d_in[9];
    const float* atts1 = (const float*)d_in[10];
    const float* attd1 = (const float*)d_in[11];
    const float* atte1 = (const float*)d_in[12];
    const float* bias1 = (const float*)d_in[13];
    const float* lin2  = (const float*)d_in[14];
    const float* line2 = (const float*)d_in[15];
    const float* atts2 = (const float*)d_in[16];
    const float* attd2 = (const float*)d_in[17];
    const float* atte2 = (const float*)d_in[18];
    const float* bias2 = (const float*)d_in[19];

    const int N = out_size / DH;          // 20000
    const int E = in_sizes[1] / 2;        // 320000
    const int F = in_sizes[3] / 256;      // 518
    const int* src = eidx;
    const int* dst = eidx + E;

    float *hidden, *h0, *h1, *as_, *ad_, *relproj;
    __half* hlinh;
    int *cnt, *ctr, *rowptr;
    int2* cedge;
    cudaGetSymbolAddress((void**)&hidden, g_hidden);
    cudaGetSymbolAddress((void**)&h0, g_h0);
    cudaGetSymbolAddress((void**)&h1, g_h1);
    cudaGetSymbolAddress((void**)&hlinh, g_hlinh);
    cudaGetSymbolAddress((void**)&as_, g_as);
    cudaGetSymbolAddress((void**)&ad_, g_ad);
    cudaGetSymbolAddress((void**)&cnt, g_cnt);
    cudaGetSymbolAddress((void**)&ctr, g_ctr);
    cudaGetSymbolAddress((void**)&rowptr, g_rowptr);
    cudaGetSymbolAddress((void**)&cedge, g_cedge);
    cudaGetSymbolAddress((void**)&relproj, g_relproj);

    // CSR build (same for both layers)
    zero2_kernel<<<(N + 255) / 256, 256>>>(cnt, ctr, N);
    hist_kernel<<<(E + 255) / 256, 256>>>(dst, E, cnt);
    scan_kernel<<<1, 1024>>>(cnt, rowptr, N);
    scatter_kernel<<<(E + 255) / 256, 256>>>(src, dst, etype, E, rowptr, ctr, cedge);

    // collapsed edge-attention tables (both layers, one launch)
    relproj_kernel<<<2, 128>>>(rel, line1, atte1, line2, atte2, relproj);

    const int MB = (N + 127) / 128;
    const int AGG_B = (N + 7) / 8;

    // node encoder
    {
        dim3 g(256 / 128, MB);
        mma_gemm<true, true, false><<<g, 256>>>(N, 256, F, x, w1, b1, hidden,
                                                nullptr, nullptr, nullptr, nullptr, nullptr);
    }
    {
        dim3 g(1, MB);
        mma_gemm<false, true, false><<<g, 256>>>(N, DH, 256, hidden, w2, b2, h0,
                                                 nullptr, nullptr, nullptr, nullptr, nullptr);
    }

    // GAT layer 1: hlin GEMM -> fp16 layout + fused attention dots
    {
        dim3 g(HD / 128, MB);
        mma_gemm<false, false, true><<<g, 256>>>(N, HD, DH, h0, lin1, nullptr, nullptr,
                                                 hlinh, atts1, attd1, as_, ad_);
    }
    gat_agg_kernel<<<AGG_B, 256>>>(hlinh, as_, ad_, rowptr, cedge,
                                   relproj, bias1, h1, N);

    // GAT layer 2
    {
        dim3 g(HD / 128, MB);
        mma_gemm<false, false, true><<<g, 256>>>(N, HD, DH, h1, lin2, nullptr, nullptr,
                                                 hlinh, atts2, attd2, as_, ad_);
    }
    gat_agg_kernel<<<AGG_B, 256>>>(hlinh, as_, ad_, rowptr, cedge,
                                   relproj + 26 * HEADS, bias2, (float*)d_out, N);
}